// round 1
// baseline (speedup 1.0000x reference)
#include <cuda_runtime.h>
#include <math.h>

// ---------------------------------------------------------------------------
// Scratch (static __device__ arrays; no allocations anywhere)
// ---------------------------------------------------------------------------
__device__ float g_kf[48u * 256u * 4096u];   // 201 MB: kf for all (ref,b)
__device__ float g_kmax[48 * 256];
__device__ float g_kinv[48 * 256];
__device__ float g_qmax[16 * 256];
__device__ float g_qinvs[16 * 256];
__device__ float g_kpbs[16 * 768 * 256];     // [b][N*CH][CH]
__device__ float g_qpb[16 * 256 * 256];
__device__ float g_sim[16 * 256 * 768];
__device__ float g_value[16 * 256 * 256];
__device__ float g_qcol[16 * 4096];
__device__ float g_cm[16u * 256u * 4096u];   // 67 MB
__device__ float g_mean[512];
__device__ float g_istd[512];

// ---------------------------------------------------------------------------
// Block reduction helper (256 threads)
// ---------------------------------------------------------------------------
__device__ __forceinline__ float blockReduce(float v, bool ismax) {
    __shared__ float sh[32];
    __syncthreads();  // safe back-to-back use
    int lane = threadIdx.x & 31, wid = threadIdx.x >> 5;
    #pragma unroll
    for (int o = 16; o; o >>= 1) {
        float t = __shfl_xor_sync(0xffffffffu, v, o);
        v = ismax ? fmaxf(v, t) : (v + t);
    }
    if (lane == 0) sh[wid] = v;
    __syncthreads();
    int nw = (blockDim.x + 31) >> 5;
    if (wid == 0) {
        v = (lane < nw) ? sh[lane] : (ismax ? -1e30f : 0.f);
        #pragma unroll
        for (int o = 16; o; o >>= 1) {
            float t = __shfl_xor_sync(0xffffffffu, v, o);
            v = ismax ? fmaxf(v, t) : (v + t);
        }
        if (lane == 0) sh[0] = v;
    }
    __syncthreads();
    return sh[0];
}

// ---------------------------------------------------------------------------
// Generic 128x128x8 fp32 GEMM, 256 threads, 8x8 microtile.
// C[r,c] = alpha * sum_k A'[r,k] * B'[k,c]  (+bias[r]) (*colscale[c])
//   A: row-major [M,K] (optionally exp-transformed per row: softmax numerator)
//   B: TB ? row-major [N,K] : row-major [K,N]
//   CONCAT (NN only): global k < Ksplit reads B, else B2 (concat along K)
// C offset per batch z: (z%modB)*sCb + (z/modB)*sCr
// All of M,N divisible by 128 and K by 8 (true for every call here).
// ---------------------------------------------------------------------------
template<bool TB, bool EXPA, bool HASBIAS, bool COLSCALE, bool CONCAT>
__global__ void __launch_bounds__(256, 2) gemm128(
    const float* __restrict__ A, const float* __restrict__ B, float* __restrict__ C,
    int M, int N, int K, long sAz, long sBz,
    int modB, long sCb, long sCr, int ldc,
    const float* __restrict__ rmax, const float* __restrict__ rinv,
    const float* __restrict__ bias, const float* __restrict__ colscale,
    const float* __restrict__ B2, long sB2z, int Ksplit, float alpha)
{
    __shared__ float As[8][128];
    __shared__ float Bs[8][128];
    const int tid = threadIdx.x;
    const int z = blockIdx.z;
    const int bm = blockIdx.y * 128;
    const int bn = blockIdx.x * 128;
    const float* Ab = A + (long)z * sAz;
    const float* Bb = B + (long)z * sBz;

    const int arow = tid >> 1;
    const int akk  = (tid & 1) * 4;
    const float* aptr = Ab + (long)(bm + arow) * K + akk;
    float smx = 0.f, siv = 1.f;
    if (EXPA) {
        smx = rmax[(long)z * M + bm + arow];
        siv = rinv[(long)z * M + bm + arow];
    }

    int brow, bcol;
    const float* bptr;
    if (TB) { brow = tid >> 1; bcol = (tid & 1) * 4;  bptr = Bb + (long)(bn + brow) * K + bcol; }
    else    { brow = tid >> 5; bcol = (tid & 31) * 4; bptr = Bb + (long)brow * N + bn + bcol; }

    float acc[8][8];
    #pragma unroll
    for (int i = 0; i < 8; i++)
        #pragma unroll
        for (int j = 0; j < 8; j++) acc[i][j] = 0.f;

    const int tx = tid & 15, ty = tid >> 4;

    for (int k0 = 0; k0 < K; k0 += 8) {
        float4 av = *reinterpret_cast<const float4*>(aptr);
        if (EXPA) {
            av.x = __expf(av.x - smx) * siv;
            av.y = __expf(av.y - smx) * siv;
            av.z = __expf(av.z - smx) * siv;
            av.w = __expf(av.w - smx) * siv;
        }
        As[akk + 0][arow] = av.x; As[akk + 1][arow] = av.y;
        As[akk + 2][arow] = av.z; As[akk + 3][arow] = av.w;
        aptr += 8;

        if (TB) {
            float4 bv = *reinterpret_cast<const float4*>(bptr);
            Bs[bcol + 0][brow] = bv.x; Bs[bcol + 1][brow] = bv.y;
            Bs[bcol + 2][brow] = bv.z; Bs[bcol + 3][brow] = bv.w;
            bptr += 8;
        } else {
            float4 bv;
            if (CONCAT) {
                int kg = k0 + brow;
                const float* src = (kg < Ksplit)
                    ? (Bb + (long)kg * N + bn + bcol)
                    : (B2 + (long)z * sB2z + (long)(kg - Ksplit) * N + bn + bcol);
                bv = *reinterpret_cast<const float4*>(src);
            } else {
                bv = *reinterpret_cast<const float4*>(bptr);
                bptr += (long)8 * N;
            }
            *reinterpret_cast<float4*>(&Bs[brow][bcol]) = bv;
        }
        __syncthreads();

        #pragma unroll
        for (int k = 0; k < 8; k++) {
            float a[8], b[8];
            *reinterpret_cast<float4*>(a)     = *reinterpret_cast<const float4*>(&As[k][ty * 8]);
            *reinterpret_cast<float4*>(a + 4) = *reinterpret_cast<const float4*>(&As[k][ty * 8 + 4]);
            *reinterpret_cast<float4*>(b)     = *reinterpret_cast<const float4*>(&Bs[k][tx * 8]);
            *reinterpret_cast<float4*>(b + 4) = *reinterpret_cast<const float4*>(&Bs[k][tx * 8 + 4]);
            #pragma unroll
            for (int i = 0; i < 8; i++)
                #pragma unroll
                for (int j = 0; j < 8; j++) acc[i][j] += a[i] * b[j];
        }
        __syncthreads();
    }

    const long coff = (long)(z % modB) * sCb + (long)(z / modB) * sCr;
    float cs[8];
    if (COLSCALE) {
        #pragma unroll
        for (int j = 0; j < 8; j++) cs[j] = colscale[(long)z * N + bn + tx * 8 + j];
    }
    #pragma unroll
    for (int i = 0; i < 8; i++) {
        const int r = bm + ty * 8 + i;
        const float bi = HASBIAS ? bias[r] : 0.f;
        float tmp[8];
        #pragma unroll
        for (int j = 0; j < 8; j++) {
            float v = acc[i][j] * alpha + bi;
            if (COLSCALE) v *= cs[j];
            tmp[j] = v;
        }
        float* cp = C + coff + (long)r * ldc + bn + tx * 8;
        *reinterpret_cast<float4*>(cp)     = *reinterpret_cast<float4*>(tmp);
        *reinterpret_cast<float4*>(cp + 4) = *reinterpret_cast<float4*>(tmp + 4);
    }
}

// ---------------------------------------------------------------------------
// Per-row softmax stats (max, 1/sum(exp)) — no materialization
// ---------------------------------------------------------------------------
__global__ void row_stats(const float* __restrict__ X, float* __restrict__ omax,
                          float* __restrict__ oinv, int len)
{
    const long row = blockIdx.x;
    const float* x = X + row * len;
    float m = -1e30f;
    for (int i = threadIdx.x; i < len; i += blockDim.x) m = fmaxf(m, x[i]);
    m = blockReduce(m, true);
    float s = 0.f;
    for (int i = threadIdx.x; i < len; i += blockDim.x) s += __expf(x[i] - m);
    s = blockReduce(s, false);
    if (threadIdx.x == 0) { omax[row] = m; oinv[row] = 1.f / s; }
}

// In-place softmax over rows of length len (sim rows, len=768)
__global__ void softmax_inplace(float* __restrict__ X, int len)
{
    const long row = blockIdx.x;
    float* x = X + row * len;
    float m = -1e30f;
    for (int i = threadIdx.x; i < len; i += blockDim.x) m = fmaxf(m, x[i]);
    m = blockReduce(m, true);
    float s = 0.f;
    for (int i = threadIdx.x; i < len; i += blockDim.x) s += __expf(x[i] - m);
    s = blockReduce(s, false);
    const float inv = 1.f / s;
    for (int i = threadIdx.x; i < len; i += blockDim.x) x[i] = __expf(x[i] - m) * inv;
}

// L2-normalize rows of length 256 (exactly 256 threads/block)
__global__ void norm_rows256(float* __restrict__ V)
{
    const long row = blockIdx.x;
    float* v = V + row * 256;
    const float x = v[threadIdx.x];
    const float s = blockReduce(x * x, false);
    v[threadIdx.x] = x * (1.f / sqrtf(s));
}

// 1/||query[b,:,n]|| per spatial position
__global__ void qcol_norm(const float* __restrict__ q, float* __restrict__ out)
{
    const int b = blockIdx.y;
    const int n = blockIdx.x * 256 + threadIdx.x;
    const float* p = q + (long)b * 256 * 4096 + n;
    float s = 0.f;
    #pragma unroll 8
    for (int c = 0; c < 256; c++) { float v = p[(long)c * 4096]; s += v * v; }
    out[b * 4096 + n] = 1.f / sqrtf(s);
}

// BatchNorm batch statistics per channel (over B,H,W = 65536 values)
__global__ void bn_stats(const float* __restrict__ y, float* __restrict__ mean,
                         float* __restrict__ istd)
{
    const int o = blockIdx.x;
    float s = 0.f, s2 = 0.f;
    for (int b = 0; b < 16; b++) {
        const float* p = y + ((long)b * 512 + o) * 4096;
        for (int i = threadIdx.x; i < 4096; i += 256) {
            float v = p[i]; s += v; s2 += v * v;
        }
    }
    s = blockReduce(s, false);
    s2 = blockReduce(s2, false);
    if (threadIdx.x == 0) {
        float mu = s * (1.f / 65536.f);
        mean[o] = mu;
        istd[o] = 1.f / sqrtf(s2 * (1.f / 65536.f) - mu * mu + 1e-5f);
    }
}

// Apply BN (gamma/beta) + ReLU in place on output [16,512,4096]
__global__ void bn_apply(float* __restrict__ y, const float* __restrict__ mean,
                         const float* __restrict__ istd, const float* __restrict__ g,
                         const float* __restrict__ b)
{
    const long i = (long)blockIdx.x * 256 + threadIdx.x;
    const int o = (int)((i >> 12) & 511);
    float v = (y[i] - mean[o]) * istd[o] * g[o] + b[o];
    y[i] = v > 0.f ? v : 0.f;
}

// ---------------------------------------------------------------------------
// Host orchestration
// ---------------------------------------------------------------------------
struct Scratch {
    float *kf, *kmax, *kinv, *qmax, *qinvs, *kpbs, *qpb, *sim, *value, *qcol, *cm, *mean, *istd;
};

static Scratch fetch_scratch() {
    Scratch s;
    cudaGetSymbolAddress((void**)&s.kf,    g_kf);
    cudaGetSymbolAddress((void**)&s.kmax,  g_kmax);
    cudaGetSymbolAddress((void**)&s.kinv,  g_kinv);
    cudaGetSymbolAddress((void**)&s.qmax,  g_qmax);
    cudaGetSymbolAddress((void**)&s.qinvs, g_qinvs);
    cudaGetSymbolAddress((void**)&s.kpbs,  g_kpbs);
    cudaGetSymbolAddress((void**)&s.qpb,   g_qpb);
    cudaGetSymbolAddress((void**)&s.sim,   g_sim);
    cudaGetSymbolAddress((void**)&s.value, g_value);
    cudaGetSymbolAddress((void**)&s.qcol,  g_qcol);
    cudaGetSymbolAddress((void**)&s.cm,    g_cm);
    cudaGetSymbolAddress((void**)&s.mean,  g_mean);
    cudaGetSymbolAddress((void**)&s.istd,  g_istd);
    return s;
}

extern "C" void kernel_launch(void* const* d_in, const int* in_sizes, int n_in,
                              void* d_out, int out_size)
{
    (void)in_sizes; (void)n_in; (void)out_size;
    static Scratch s = fetch_scratch();  // resolved on the (non-captured) correctness call

    const float* x     = (const float*)d_in[0];
    const float* query = (const float*)d_in[1];
    const float* refs  = (const float*)d_in[2];
    const float* K_w   = (const float*)d_in[3];
    const float* K_b   = (const float*)d_in[4];
    // d_in[5], d_in[6] = V_w, V_b : dead code in the reference, skipped.
    const float* f_w   = (const float*)d_in[7];
    const float* f_b   = (const float*)d_in[8];
    const float* bn_g  = (const float*)d_in[9];
    const float* bn_b  = (const float*)d_in[10];
    float* out = (float*)d_out;

    // 1) kf[z] = K_w @ refs[z] + K_b  for z = ref*16+b  (48 GEMMs M256 K512 N4096)
    gemm128<false, false, true, false, false><<<dim3(32, 2, 48), 256>>>(
        K_w, refs, s.kf, 256, 4096, 512, 0, 512L * 4096,
        48, 256L * 4096, 0, 4096,
        nullptr, nullptr, K_b, nullptr, nullptr, 0, 0, 1.f);

    // 2) softmax row stats for kf and query
    row_stats<<<48 * 256, 256>>>(s.kf, s.kmax, s.kinv, 4096);
    row_stats<<<16 * 256, 256>>>(query, s.qmax, s.qinvs, 4096);

    // 3) k_pb[z] = softmax(kf[z]) @ kf[z]^T  -> scattered into k_pbs[b][ref*256+k][c]
    gemm128<true, true, false, false, false><<<dim3(2, 2, 48), 256>>>(
        s.kf, s.kf, s.kpbs, 256, 256, 4096, 256L * 4096, 256L * 4096,
        16, 768L * 256, 256L * 256, 256,
        s.kmax, s.kinv, nullptr, nullptr, nullptr, 0, 0, 1.f);

    // 4) q_pb[b] = softmax(query[b]) @ query[b]^T
    gemm128<true, true, false, false, false><<<dim3(2, 2, 16), 256>>>(
        query, query, s.qpb, 256, 256, 4096, 256L * 4096, 256L * 4096,
        16, 256L * 256, 0, 256,
        s.qmax, s.qinvs, nullptr, nullptr, nullptr, 0, 0, 1.f);

    // 5) sim = (q_pb @ k_pbs^T) / sqrt(256)
    gemm128<true, false, false, false, false><<<dim3(6, 2, 16), 256>>>(
        s.qpb, s.kpbs, s.sim, 256, 768, 256, 256L * 256, 768L * 256,
        16, 256L * 768, 0, 768,
        nullptr, nullptr, nullptr, nullptr, nullptr, 0, 0, 0.0625f);

    // 6) softmax over k (768)
    softmax_inplace<<<16 * 256, 256>>>(s.sim, 768);

    // 7) value = sim @ k_pbs  (v_pbs == k_pbs per reference)
    gemm128<false, false, false, false, false><<<dim3(2, 2, 16), 256>>>(
        s.sim, s.kpbs, s.value, 256, 256, 768, 256L * 768, 768L * 256,
        16, 256L * 256, 0, 256,
        nullptr, nullptr, nullptr, nullptr, nullptr, 0, 0, 1.f);

    // 8) row-normalize value (proto), column norms of query
    norm_rows256<<<16 * 256, 256>>>(s.value);
    qcol_norm<<<dim3(16, 16), 256>>>(query, s.qcol);

    // 9) cm = proto_n @ query, columns scaled by 1/||q col||
    gemm128<false, false, false, true, false><<<dim3(32, 2, 16), 256>>>(
        s.value, query, s.cm, 256, 4096, 256, 256L * 256, 256L * 4096,
        16, 256L * 4096, 0, 4096,
        nullptr, nullptr, nullptr, s.qcol, nullptr, 0, 0, 1.f);

    // 10) y = f_w @ concat(x, cm) + f_b  (K=768, virtual concat in the B loader)
    gemm128<false, false, true, false, true><<<dim3(32, 4, 16), 256>>>(
        f_w, x, out, 512, 4096, 768, 0, 512L * 4096,
        16, 512L * 4096, 0, 4096,
        nullptr, nullptr, f_b, nullptr, s.cm, 256L * 4096, 512, 1.f);

    // 11) BatchNorm (batch stats) + ReLU in place
    bn_stats<<<512, 256>>>(out, s.mean, s.istd);
    bn_apply<<<131072, 256>>>(out, s.mean, s.istd, bn_g, bn_b);
}

// round 2
// speedup vs baseline: 1.0174x; 1.0174x over previous
#include <cuda_runtime.h>
#include <math.h>

// ---------------------------------------------------------------------------
// Scratch (static __device__ arrays; no allocations anywhere)
// ---------------------------------------------------------------------------
__device__ float g_kf[48u * 256u * 4096u];   // 201 MB: kf for all (ref,b)
__device__ float g_kmax[48 * 256];
__device__ float g_kinv[48 * 256];
__device__ float g_qmax[16 * 256];
__device__ float g_qinvs[16 * 256];
__device__ float g_kpbs[16 * 768 * 256];     // [b][N*CH][CH]
__device__ float g_qpb[16 * 256 * 256];
__device__ float g_sim[16 * 256 * 768];
__device__ float g_value[16 * 256 * 256];
__device__ float g_qcol[16 * 4096];
__device__ float g_cm[16u * 256u * 4096u];   // 67 MB
__device__ float g_mean[512];
__device__ float g_istd[512];

// ---------------------------------------------------------------------------
// Block reduction helper (256 threads)
// ---------------------------------------------------------------------------
__device__ __forceinline__ float blockReduce(float v, bool ismax) {
    __shared__ float sh[32];
    __syncthreads();  // safe back-to-back use
    int lane = threadIdx.x & 31, wid = threadIdx.x >> 5;
    #pragma unroll
    for (int o = 16; o; o >>= 1) {
        float t = __shfl_xor_sync(0xffffffffu, v, o);
        v = ismax ? fmaxf(v, t) : (v + t);
    }
    if (lane == 0) sh[wid] = v;
    __syncthreads();
    int nw = (blockDim.x + 31) >> 5;
    if (wid == 0) {
        v = (lane < nw) ? sh[lane] : (ismax ? -1e30f : 0.f);
        #pragma unroll
        for (int o = 16; o; o >>= 1) {
            float t = __shfl_xor_sync(0xffffffffu, v, o);
            v = ismax ? fmaxf(v, t) : (v + t);
        }
        if (lane == 0) sh[0] = v;
    }
    __syncthreads();
    return sh[0];
}

// ---------------------------------------------------------------------------
// 128x128x8 fp32 GEMM, 256 threads, 8x8 microtile via packed f32x2 FFMA2.
// Double-buffered smem, one __syncthreads per K-chunk.
// C[r,c] = alpha * sum_k A'[r,k] * B'[k,c]  (+bias[r]) (*colscale[c])
//   A: row-major [M,K] (EXPA: per-row softmax transform exp(a-max)*inv fused)
//   B: TB ? row-major [N,K] : row-major [K,N]
//   CONCAT (NN only): global k < Ksplit reads B, else B2 (concat along K)
// C offset per batch z: (z%modB)*sCb + (z/modB)*sCr
// All of M,N divisible by 128 and K by 8 (true for every call here).
// ---------------------------------------------------------------------------
template<bool TB, bool EXPA, bool HASBIAS, bool COLSCALE, bool CONCAT>
__global__ void __launch_bounds__(256, 2) gemm128(
    const float* __restrict__ A, const float* __restrict__ B, float* __restrict__ C,
    int M, int N, int K, long sAz, long sBz,
    int modB, long sCb, long sCr, int ldc,
    const float* __restrict__ rmax, const float* __restrict__ rinv,
    const float* __restrict__ bias, const float* __restrict__ colscale,
    const float* __restrict__ B2, long sB2z, int Ksplit, float alpha)
{
    __shared__ __align__(16) float As[2][8][132];  // pad 132 kills staging conflicts
    __shared__ __align__(16) float Bs[2][8][132];
    const int tid = threadIdx.x;
    const int z = blockIdx.z;
    const int bm = blockIdx.y * 128;
    const int bn = blockIdx.x * 128;
    const float* Ab = A + (long)z * sAz;
    const float* Bb = B + (long)z * sBz;

    const int arow = tid >> 1;
    const int akk  = (tid & 1) * 4;
    const float* aptr = Ab + (long)(bm + arow) * K + akk;
    float smx = 0.f, siv = 1.f;
    if (EXPA) {
        smx = rmax[(long)z * M + bm + arow];
        siv = rinv[(long)z * M + bm + arow];
    }

    int brow, bcol;
    const float* bptr = nullptr;
    if (TB) { brow = tid >> 1; bcol = (tid & 1) * 4;  bptr = Bb + (long)(bn + brow) * K + bcol; }
    else    { brow = tid >> 5; bcol = (tid & 31) * 4; bptr = Bb + (long)brow * N + bn + bcol; }

    const int tx = tid & 15, ty = tid >> 4;
    const int nch = K >> 3;

    auto loadA = [&](int ch) -> float4 {
        float4 av = *reinterpret_cast<const float4*>(aptr + ch * 8);
        if (EXPA) {
            av.x = __expf(av.x - smx) * siv;
            av.y = __expf(av.y - smx) * siv;
            av.z = __expf(av.z - smx) * siv;
            av.w = __expf(av.w - smx) * siv;
        }
        return av;
    };
    auto loadB = [&](int ch) -> float4 {
        if (TB) {
            return *reinterpret_cast<const float4*>(bptr + ch * 8);
        } else if (CONCAT) {
            const int kg = ch * 8 + brow;
            const float* src = (kg < Ksplit)
                ? (Bb + (long)kg * N + bn + bcol)
                : (B2 + (long)z * sB2z + (long)(kg - Ksplit) * N + bn + bcol);
            return *reinterpret_cast<const float4*>(src);
        } else {
            return *reinterpret_cast<const float4*>(bptr + (long)ch * 8 * N);
        }
    };
    auto stash = [&](int buf, float4 av, float4 bv) {
        As[buf][akk + 0][arow] = av.x; As[buf][akk + 1][arow] = av.y;
        As[buf][akk + 2][arow] = av.z; As[buf][akk + 3][arow] = av.w;
        if (TB) {
            Bs[buf][bcol + 0][brow] = bv.x; Bs[buf][bcol + 1][brow] = bv.y;
            Bs[buf][bcol + 2][brow] = bv.z; Bs[buf][bcol + 3][brow] = bv.w;
        } else {
            *reinterpret_cast<float4*>(&Bs[buf][brow][bcol]) = bv;
        }
    };

    // acc2[i2][j] holds fp32 pair (row 2*i2, row 2*i2+1) for column j
    unsigned long long acc2[4][8];
    #pragma unroll
    for (int i = 0; i < 4; i++)
        #pragma unroll
        for (int j = 0; j < 8; j++) acc2[i][j] = 0ull;

    stash(0, loadA(0), loadB(0));
    __syncthreads();

    int cur = 0;
    for (int ch = 0; ch < nch; ch++) {
        const bool hasNext = (ch + 1 < nch);
        float4 avn, bvn;
        if (hasNext) { avn = loadA(ch + 1); bvn = loadB(ch + 1); }

        const float (*Ac)[132] = As[cur];
        const float (*Bc)[132] = Bs[cur];
        #pragma unroll
        for (int k = 0; k < 8; k++) {
            unsigned long long a2[4];
            {
                ulonglong2 t0 = *reinterpret_cast<const ulonglong2*>(&Ac[k][ty * 8]);
                ulonglong2 t1 = *reinterpret_cast<const ulonglong2*>(&Ac[k][ty * 8 + 4]);
                a2[0] = t0.x; a2[1] = t0.y; a2[2] = t1.x; a2[3] = t1.y;
            }
            float b[8];
            *reinterpret_cast<float4*>(b)     = *reinterpret_cast<const float4*>(&Bc[k][tx * 8]);
            *reinterpret_cast<float4*>(b + 4) = *reinterpret_cast<const float4*>(&Bc[k][tx * 8 + 4]);
            unsigned long long b2[8];
            #pragma unroll
            for (int j = 0; j < 8; j++)
                asm("mov.b64 %0, {%1, %1};" : "=l"(b2[j]) : "f"(b[j]));
            #pragma unroll
            for (int i = 0; i < 4; i++)
                #pragma unroll
                for (int j = 0; j < 8; j++)
                    asm("fma.rn.f32x2 %0, %1, %2, %0;"
                        : "+l"(acc2[i][j]) : "l"(a2[i]), "l"(b2[j]));
        }
        if (hasNext) stash(cur ^ 1, avn, bvn);
        __syncthreads();
        cur ^= 1;
    }

    const long coff = (long)(z % modB) * sCb + (long)(z / modB) * sCr;
    float cs[8];
    if (COLSCALE) {
        #pragma unroll
        for (int j = 0; j < 8; j++) cs[j] = colscale[(long)z * N + bn + tx * 8 + j];
    }
    #pragma unroll
    for (int i = 0; i < 8; i++) {
        const int r = bm + ty * 8 + i;
        const float bi = HASBIAS ? bias[r] : 0.f;
        float tmp[8];
        #pragma unroll
        for (int j = 0; j < 8; j++) {
            float lo, hi;
            asm("mov.b64 {%0, %1}, %2;" : "=f"(lo), "=f"(hi) : "l"(acc2[i >> 1][j]));
            float v = ((i & 1) ? hi : lo) * alpha + bi;
            if (COLSCALE) v *= cs[j];
            tmp[j] = v;
        }
        float* cp = C + coff + (long)r * ldc + bn + tx * 8;
        *reinterpret_cast<float4*>(cp)     = *reinterpret_cast<float4*>(tmp);
        *reinterpret_cast<float4*>(cp + 4) = *reinterpret_cast<float4*>(tmp + 4);
    }
}

// ---------------------------------------------------------------------------
// Per-row softmax stats (max, 1/sum(exp)) — no materialization
// ---------------------------------------------------------------------------
__global__ void row_stats(const float* __restrict__ X, float* __restrict__ omax,
                          float* __restrict__ oinv, int len)
{
    const long row = blockIdx.x;
    const float* x = X + row * len;
    float m = -1e30f;
    for (int i = threadIdx.x; i < len; i += blockDim.x) m = fmaxf(m, x[i]);
    m = blockReduce(m, true);
    float s = 0.f;
    for (int i = threadIdx.x; i < len; i += blockDim.x) s += __expf(x[i] - m);
    s = blockReduce(s, false);
    if (threadIdx.x == 0) { omax[row] = m; oinv[row] = 1.f / s; }
}

// In-place softmax over rows of length len (sim rows, len=768)
__global__ void softmax_inplace(float* __restrict__ X, int len)
{
    const long row = blockIdx.x;
    float* x = X + row * len;
    float m = -1e30f;
    for (int i = threadIdx.x; i < len; i += blockDim.x) m = fmaxf(m, x[i]);
    m = blockReduce(m, true);
    float s = 0.f;
    for (int i = threadIdx.x; i < len; i += blockDim.x) s += __expf(x[i] - m);
    s = blockReduce(s, false);
    const float inv = 1.f / s;
    for (int i = threadIdx.x; i < len; i += blockDim.x) x[i] = __expf(x[i] - m) * inv;
}

// L2-normalize rows of length 256 (exactly 256 threads/block)
__global__ void norm_rows256(float* __restrict__ V)
{
    const long row = blockIdx.x;
    float* v = V + row * 256;
    const float x = v[threadIdx.x];
    const float s = blockReduce(x * x, false);
    v[threadIdx.x] = x * (1.f / sqrtf(s));
}

// 1/||query[b,:,n]|| per spatial position
__global__ void qcol_norm(const float* __restrict__ q, float* __restrict__ out)
{
    const int b = blockIdx.y;
    const int n = blockIdx.x * 256 + threadIdx.x;
    const float* p = q + (long)b * 256 * 4096 + n;
    float s = 0.f;
    #pragma unroll 8
    for (int c = 0; c < 256; c++) { float v = p[(long)c * 4096]; s += v * v; }
    out[b * 4096 + n] = 1.f / sqrtf(s);
}

// BatchNorm batch statistics per channel (over B,H,W = 65536 values)
__global__ void bn_stats(const float* __restrict__ y, float* __restrict__ mean,
                         float* __restrict__ istd)
{
    const int o = blockIdx.x;
    float s = 0.f, s2 = 0.f;
    for (int b = 0; b < 16; b++) {
        const float* p = y + ((long)b * 512 + o) * 4096;
        for (int i = threadIdx.x; i < 4096; i += 256) {
            float v = p[i]; s += v; s2 += v * v;
        }
    }
    s = blockReduce(s, false);
    s2 = blockReduce(s2, false);
    if (threadIdx.x == 0) {
        float mu = s * (1.f / 65536.f);
        mean[o] = mu;
        istd[o] = 1.f / sqrtf(s2 * (1.f / 65536.f) - mu * mu + 1e-5f);
    }
}

// Apply BN (gamma/beta) + ReLU in place on output [16,512,4096]
__global__ void bn_apply(float* __restrict__ y, const float* __restrict__ mean,
                         const float* __restrict__ istd, const float* __restrict__ g,
                         const float* __restrict__ b)
{
    const long i = (long)blockIdx.x * 256 + threadIdx.x;
    const int o = (int)((i >> 12) & 511);
    float v = (y[i] - mean[o]) * istd[o] * g[o] + b[o];
    y[i] = v > 0.f ? v : 0.f;
}

// ---------------------------------------------------------------------------
// Host orchestration
// ---------------------------------------------------------------------------
struct Scratch {
    float *kf, *kmax, *kinv, *qmax, *qinvs, *kpbs, *qpb, *sim, *value, *qcol, *cm, *mean, *istd;
};

static Scratch fetch_scratch() {
    Scratch s;
    cudaGetSymbolAddress((void**)&s.kf,    g_kf);
    cudaGetSymbolAddress((void**)&s.kmax,  g_kmax);
    cudaGetSymbolAddress((void**)&s.kinv,  g_kinv);
    cudaGetSymbolAddress((void**)&s.qmax,  g_qmax);
    cudaGetSymbolAddress((void**)&s.qinvs, g_qinvs);
    cudaGetSymbolAddress((void**)&s.kpbs,  g_kpbs);
    cudaGetSymbolAddress((void**)&s.qpb,   g_qpb);
    cudaGetSymbolAddress((void**)&s.sim,   g_sim);
    cudaGetSymbolAddress((void**)&s.value, g_value);
    cudaGetSymbolAddress((void**)&s.qcol,  g_qcol);
    cudaGetSymbolAddress((void**)&s.cm,    g_cm);
    cudaGetSymbolAddress((void**)&s.mean,  g_mean);
    cudaGetSymbolAddress((void**)&s.istd,  g_istd);
    return s;
}

extern "C" void kernel_launch(void* const* d_in, const int* in_sizes, int n_in,
                              void* d_out, int out_size)
{
    (void)in_sizes; (void)n_in; (void)out_size;
    static Scratch s = fetch_scratch();  // resolved on the (non-captured) correctness call

    const float* x     = (const float*)d_in[0];
    const float* query = (const float*)d_in[1];
    const float* refs  = (const float*)d_in[2];
    const float* K_w   = (const float*)d_in[3];
    const float* K_b   = (const float*)d_in[4];
    // d_in[5], d_in[6] = V_w, V_b : dead code in the reference, skipped.
    const float* f_w   = (const float*)d_in[7];
    const float* f_b   = (const float*)d_in[8];
    const float* bn_g  = (const float*)d_in[9];
    const float* bn_b  = (const float*)d_in[10];
    float* out = (float*)d_out;

    // 1) kf[z] = K_w @ refs[z] + K_b  for z = ref*16+b  (48 GEMMs M256 K512 N4096)
    gemm128<false, false, true, false, false><<<dim3(32, 2, 48), 256>>>(
        K_w, refs, s.kf, 256, 4096, 512, 0, 512L * 4096,
        48, 256L * 4096, 0, 4096,
        nullptr, nullptr, K_b, nullptr, nullptr, 0, 0, 1.f);

    // 2) softmax row stats for kf and query
    row_stats<<<48 * 256, 256>>>(s.kf, s.kmax, s.kinv, 4096);
    row_stats<<<16 * 256, 256>>>(query, s.qmax, s.qinvs, 4096);

    // 3) k_pb[z] = softmax(kf[z]) @ kf[z]^T  -> scattered into k_pbs[b][ref*256+k][c]
    gemm128<true, true, false, false, false><<<dim3(2, 2, 48), 256>>>(
        s.kf, s.kf, s.kpbs, 256, 256, 4096, 256L * 4096, 256L * 4096,
        16, 768L * 256, 256L * 256, 256,
        s.kmax, s.kinv, nullptr, nullptr, nullptr, 0, 0, 1.f);

    // 4) q_pb[b] = softmax(query[b]) @ query[b]^T
    gemm128<true, true, false, false, false><<<dim3(2, 2, 16), 256>>>(
        query, query, s.qpb, 256, 256, 4096, 256L * 4096, 256L * 4096,
        16, 256L * 256, 0, 256,
        s.qmax, s.qinvs, nullptr, nullptr, nullptr, 0, 0, 1.f);

    // 5) sim = (q_pb @ k_pbs^T) / sqrt(256)
    gemm128<true, false, false, false, false><<<dim3(6, 2, 16), 256>>>(
        s.qpb, s.kpbs, s.sim, 256, 768, 256, 256L * 256, 768L * 256,
        16, 256L * 768, 0, 768,
        nullptr, nullptr, nullptr, nullptr, nullptr, 0, 0, 0.0625f);

    // 6) softmax over k (768)
    softmax_inplace<<<16 * 256, 256>>>(s.sim, 768);

    // 7) value = sim @ k_pbs  (v_pbs == k_pbs per reference)
    gemm128<false, false, false, false, false><<<dim3(2, 2, 16), 256>>>(
        s.sim, s.kpbs, s.value, 256, 256, 768, 256L * 768, 768L * 256,
        16, 256L * 256, 0, 256,
        nullptr, nullptr, nullptr, nullptr, nullptr, 0, 0, 1.f);

    // 8) row-normalize value (proto), column norms of query
    norm_rows256<<<16 * 256, 256>>>(s.value);
    qcol_norm<<<dim3(16, 16), 256>>>(query, s.qcol);

    // 9) cm = proto_n @ query, columns scaled by 1/||q col||
    gemm128<false, false, false, true, false><<<dim3(32, 2, 16), 256>>>(
        s.value, query, s.cm, 256, 4096, 256, 256L * 256, 256L * 4096,
        16, 256L * 4096, 0, 4096,
        nullptr, nullptr, nullptr, s.qcol, nullptr, 0, 0, 1.f);

    // 10) y = f_w @ concat(x, cm) + f_b  (K=768, virtual concat in the B loader)
    gemm128<false, false, true, false, true><<<dim3(32, 4, 16), 256>>>(
        f_w, x, out, 512, 4096, 768, 0, 512L * 4096,
        16, 512L * 4096, 0, 4096,
        nullptr, nullptr, f_b, nullptr, s.cm, 256L * 4096, 512, 1.f);

    // 11) BatchNorm (batch stats) + ReLU in place
    bn_stats<<<512, 256>>>(out, s.mean, s.istd);
    bn_apply<<<131072, 256>>>(out, s.mean, s.istd, bn_g, bn_b);
}

// round 5
// speedup vs baseline: 1.2008x; 1.1802x over previous
#include <cuda_runtime.h>
#include <cuda_bf16.h>
#include <cstdint>
#include <stdint.h>
#include <math.h>

// ---------------------------------------------------------------------------
// Scratch (static __device__ arrays; no allocations anywhere)
// ---------------------------------------------------------------------------
__device__ float g_kf[48u * 256u * 4096u];   // 201 MB
__device__ float g_kmax[48 * 256];
__device__ float g_kinv[48 * 256];
__device__ float g_qmax[16 * 256];
__device__ float g_qinvs[16 * 256];
__device__ float g_kpbs[16 * 768 * 256];
__device__ float g_qpb[16 * 256 * 256];
__device__ float g_sim[16 * 256 * 768];
__device__ float g_value[16 * 256 * 256];
__device__ float g_qcol[16 * 4096];
__device__ float g_cm[16u * 256u * 4096u];   // 67 MB
__device__ float g_mean[512];
__device__ float g_istd[512];

// ---------------------------------------------------------------------------
// mma.sync helpers (plain sm_80+ PTX — valid under compute_103)
// ---------------------------------------------------------------------------
__device__ __forceinline__ uint32_t smem_u32(const void* p) {
    uint32_t a;
    asm("{ .reg .u64 t; cvta.to.shared.u64 t, %1; cvt.u32.u64 %0, t; }" : "=r"(a) : "l"(p));
    return a;
}
__device__ __forceinline__ void ldmat4(uint32_t& r0, uint32_t& r1, uint32_t& r2, uint32_t& r3,
                                       uint32_t addr) {
    asm volatile("ldmatrix.sync.aligned.m8n8.x4.shared.b16 {%0,%1,%2,%3}, [%4];"
                 : "=r"(r0), "=r"(r1), "=r"(r2), "=r"(r3) : "r"(addr));
}
__device__ __forceinline__ void mma16816(float* d, const uint32_t* a, const uint32_t* b) {
    asm volatile(
        "mma.sync.aligned.m16n8k16.row.col.f32.bf16.bf16.f32 "
        "{%0,%1,%2,%3}, {%4,%5,%6,%7}, {%8,%9}, {%0,%1,%2,%3};"
        : "+f"(d[0]), "+f"(d[1]), "+f"(d[2]), "+f"(d[3])
        : "r"(a[0]), "r"(a[1]), "r"(a[2]), "r"(a[3]), "r"(b[0]), "r"(b[1]));
}

// split fp32 -> bf16 hi + bf16 residual
__device__ __forceinline__ void split2(float f, unsigned short& u1, unsigned short& u2) {
    __nv_bfloat16 h1 = __float2bfloat16(f);
    float r = f - __bfloat162float(h1);
    __nv_bfloat16 h2 = __float2bfloat16(r);
    u1 = *reinterpret_cast<unsigned short*>(&h1);
    u2 = *reinterpret_cast<unsigned short*>(&h2);
}

// smem geometry: 4 bf16 tiles [128 rows x 32 k] with 40-element rows (80 B),
// parts: A1, A2, B1, B2; double buffered.
static constexpr int ROWB   = 80;       // bytes per smem row (32 bf16 + 8 pad)
static constexpr int PARTB  = 128 * ROWB;      // 10240 B per part
static constexpr int BUFB   = 4 * PARTB;       // 40960 B per buffer
static constexpr int TG_SMEM = 2 * BUFB;       // 81920 B

// ---------------------------------------------------------------------------
// mma.sync bf16-split2 GEMM: C = alpha*(A' @ B') (+bias[r])
//   A: row-major [M,K]; EXPA: fused exp(a - rmax)*rinv per row
//   TB:  B row-major [N,K]   (C = A @ B^T)
//   !TB: B row-major [K,N]   (C = A @ B), transposed into smem
//   CONCAT (!TB only): k >= Ksplit reads B2 (per z) scaled by colscale[z*N+n]
// CTA tile 128x128, K chunks of 32. M,N % 128 == 0, K % 32 == 0.
// ---------------------------------------------------------------------------
template<bool TB, bool EXPA, bool HASBIAS, bool CONCAT>
__global__ void __launch_bounds__(256, 1) mgemm(
    const float* __restrict__ A, const float* __restrict__ B, float* __restrict__ C,
    int M, int N, int K, long sAz, long sBz,
    int modB, long sCb, long sCr, int ldc,
    const float* __restrict__ rmax, const float* __restrict__ rinv,
    const float* __restrict__ bias,
    const float* __restrict__ B2, long sB2z, int Ksplit,
    const float* __restrict__ colscale, float alpha)
{
    extern __shared__ char smem[];
    const uint32_t sb = smem_u32(smem);
    const int tid = threadIdx.x;
    const int wid = tid >> 5;
    const int lane = tid & 31;
    const int z = blockIdx.z;
    const int bm = blockIdx.y * 128;
    const int bn = blockIdx.x * 128;
    const float* Ab = A + (long)z * sAz;
    const float* Bb = B + (long)z * sBz;

    // EXPA row stats: A loader rows are (tid>>3)+32j, fixed across chunks
    float smx[4], siv[4];
    if (EXPA) {
        #pragma unroll
        for (int j = 0; j < 4; j++) {
            const int r = bm + (tid >> 3) + 32 * j;
            smx[j] = rmax[(long)z * M + r];
            siv[j] = rinv[(long)z * M + r];
        }
    }

    const int nch = K >> 5;

    auto loadA = [&](int k0, float4* fa) {
        #pragma unroll
        for (int j = 0; j < 4; j++) {
            const int row = (tid >> 3) + 32 * j;
            const int c4 = tid & 7;
            fa[j] = *reinterpret_cast<const float4*>(Ab + (long)(bm + row) * K + k0 + c4 * 4);
        }
    };
    auto loadB = [&](int k0, float4* fb) {
        if (TB) {
            #pragma unroll
            for (int j = 0; j < 4; j++) {
                const int row = (tid >> 3) + 32 * j;
                const int c4 = tid & 7;
                fb[j] = *reinterpret_cast<const float4*>(Bb + (long)(bn + row) * K + k0 + c4 * 4);
            }
        } else {
            #pragma unroll
            for (int j = 0; j < 4; j++) {
                const int k = ((tid + 256 * j) >> 5);
                const int n4 = tid & 31;
                const int kg = k0 + k;
                float4 f;
                if (CONCAT && kg >= Ksplit) {
                    f = *reinterpret_cast<const float4*>(
                        B2 + (long)z * sB2z + (long)(kg - Ksplit) * N + bn + n4 * 4);
                    const float4 c = *reinterpret_cast<const float4*>(
                        colscale + (long)z * N + bn + n4 * 4);
                    f.x *= c.x; f.y *= c.y; f.z *= c.z; f.w *= c.w;
                } else {
                    f = *reinterpret_cast<const float4*>(Bb + (long)kg * N + bn + n4 * 4);
                }
                fb[j] = f;
            }
        }
    };
    auto stashA = [&](int buf, const float4* fa) {
        char* a1 = smem + buf * BUFB;
        char* a2 = a1 + PARTB;
        #pragma unroll
        for (int j = 0; j < 4; j++) {
            const int row = (tid >> 3) + 32 * j;
            const int c4 = tid & 7;
            float4 f = fa[j];
            if (EXPA) {
                const float m = smx[j], v = siv[j];
                f.x = __expf(f.x - m) * v; f.y = __expf(f.y - m) * v;
                f.z = __expf(f.z - m) * v; f.w = __expf(f.w - m) * v;
            }
            unsigned short x1, x2, y1, y2, z1, z2, w1, w2;
            split2(f.x, x1, x2); split2(f.y, y1, y2);
            split2(f.z, z1, z2); split2(f.w, w1, w2);
            const int off = row * ROWB + c4 * 8;
            *reinterpret_cast<uint2*>(a1 + off) =
                make_uint2((uint32_t)x1 | ((uint32_t)y1 << 16), (uint32_t)z1 | ((uint32_t)w1 << 16));
            *reinterpret_cast<uint2*>(a2 + off) =
                make_uint2((uint32_t)x2 | ((uint32_t)y2 << 16), (uint32_t)z2 | ((uint32_t)w2 << 16));
        }
    };
    auto stashB = [&](int buf, const float4* fb) {
        char* b1 = smem + buf * BUFB + 2 * PARTB;
        char* b2 = b1 + PARTB;
        if (TB) {
            #pragma unroll
            for (int j = 0; j < 4; j++) {
                const int row = (tid >> 3) + 32 * j;
                const int c4 = tid & 7;
                const float4 f = fb[j];
                unsigned short x1, x2, y1, y2, z1, z2, w1, w2;
                split2(f.x, x1, x2); split2(f.y, y1, y2);
                split2(f.z, z1, z2); split2(f.w, w1, w2);
                const int off = row * ROWB + c4 * 8;
                *reinterpret_cast<uint2*>(b1 + off) =
                    make_uint2((uint32_t)x1 | ((uint32_t)y1 << 16), (uint32_t)z1 | ((uint32_t)w1 << 16));
                *reinterpret_cast<uint2*>(b2 + off) =
                    make_uint2((uint32_t)x2 | ((uint32_t)y2 << 16), (uint32_t)z2 | ((uint32_t)w2 << 16));
            }
        } else {
            #pragma unroll
            for (int j = 0; j < 4; j++) {
                const int k = ((tid + 256 * j) >> 5);
                const int n4 = tid & 31;
                const float ff[4] = {fb[j].x, fb[j].y, fb[j].z, fb[j].w};
                #pragma unroll
                for (int u = 0; u < 4; u++) {
                    unsigned short u1, u2;
                    split2(ff[u], u1, u2);
                    const int off = (n4 * 4 + u) * ROWB + k * 2;
                    *reinterpret_cast<unsigned short*>(b1 + off) = u1;
                    *reinterpret_cast<unsigned short*>(b2 + off) = u2;
                }
            }
        }
    };

    // prologue: chunk 0
    float4 fa[4], fb[4];
    loadA(0, fa); loadB(0, fb);
    stashA(0, fa); stashB(0, fb);
    __syncthreads();

    float d[4][4][4];
    #pragma unroll
    for (int i = 0; i < 4; i++)
        #pragma unroll
        for (int j = 0; j < 4; j++)
            #pragma unroll
            for (int q = 0; q < 4; q++) d[i][j][q] = 0.f;

    const int wm = (wid >> 2) * 64;   // warp m offset in tile
    const int wn = (wid & 3) * 32;    // warp n offset
    const int lr = lane & 15;
    const int lc = lane >> 4;

    for (int ch = 0; ch < nch; ch++) {
        const bool hasNext = (ch + 1 < nch);
        if (hasNext) { loadA((ch + 1) * 32, fa); loadB((ch + 1) * 32, fb); }

        const uint32_t base = sb + (ch & 1) * BUFB;
        #pragma unroll
        for (int ks = 0; ks < 2; ks++) {
            const uint32_t koff = ks * 32 + lc * 16;
            uint32_t ah[4][4], al[4][4], bh[4][2], bl[4][2];
            #pragma unroll
            for (int mt = 0; mt < 4; mt++)
                ldmat4(ah[mt][0], ah[mt][1], ah[mt][2], ah[mt][3],
                       base + (wm + mt * 16 + lr) * ROWB + koff);
            #pragma unroll
            for (int bt = 0; bt < 2; bt++) {
                uint32_t r0, r1, r2, r3;
                ldmat4(r0, r1, r2, r3, base + 2 * PARTB + (wn + bt * 16 + lr) * ROWB + koff);
                bh[2 * bt][0] = r0; bh[2 * bt][1] = r2;
                bh[2 * bt + 1][0] = r1; bh[2 * bt + 1][1] = r3;
            }
            // hi*hi
            #pragma unroll
            for (int mt = 0; mt < 4; mt++)
                #pragma unroll
                for (int nt = 0; nt < 4; nt++) mma16816(d[mt][nt], ah[mt], bh[nt]);
            // hi*lo
            #pragma unroll
            for (int bt = 0; bt < 2; bt++) {
                uint32_t r0, r1, r2, r3;
                ldmat4(r0, r1, r2, r3, base + 3 * PARTB + (wn + bt * 16 + lr) * ROWB + koff);
                bl[2 * bt][0] = r0; bl[2 * bt][1] = r2;
                bl[2 * bt + 1][0] = r1; bl[2 * bt + 1][1] = r3;
            }
            #pragma unroll
            for (int mt = 0; mt < 4; mt++)
                #pragma unroll
                for (int nt = 0; nt < 4; nt++) mma16816(d[mt][nt], ah[mt], bl[nt]);
            // lo*hi
            #pragma unroll
            for (int mt = 0; mt < 4; mt++)
                ldmat4(al[mt][0], al[mt][1], al[mt][2], al[mt][3],
                       base + PARTB + (wm + mt * 16 + lr) * ROWB + koff);
            #pragma unroll
            for (int mt = 0; mt < 4; mt++)
                #pragma unroll
                for (int nt = 0; nt < 4; nt++) mma16816(d[mt][nt], al[mt], bh[nt]);
        }
        if (hasNext) { stashA((ch + 1) & 1, fa); stashB((ch + 1) & 1, fb); }
        __syncthreads();
    }

    // epilogue
    const long coff = (long)(z % modB) * sCb + (long)(z / modB) * sCr;
    #pragma unroll
    for (int mt = 0; mt < 4; mt++) {
        const int r0 = bm + wm + mt * 16 + (lane >> 2);
        const float bi0 = HASBIAS ? bias[r0] : 0.f;
        const float bi8 = HASBIAS ? bias[r0 + 8] : 0.f;
        #pragma unroll
        for (int nt = 0; nt < 4; nt++) {
            const int c0 = bn + wn + nt * 8 + (lane & 3) * 2;
            float* p0 = C + coff + (long)r0 * ldc + c0;
            float* p1 = C + coff + (long)(r0 + 8) * ldc + c0;
            *reinterpret_cast<float2*>(p0) =
                make_float2(d[mt][nt][0] * alpha + bi0, d[mt][nt][1] * alpha + bi0);
            *reinterpret_cast<float2*>(p1) =
                make_float2(d[mt][nt][2] * alpha + bi8, d[mt][nt][3] * alpha + bi8);
        }
    }
}

// ---------------------------------------------------------------------------
// Reductions / elementwise helpers
// ---------------------------------------------------------------------------
__device__ __forceinline__ float blockReduce(float v, bool ismax) {
    __shared__ float sh[32];
    __syncthreads();
    int lane = threadIdx.x & 31, wid = threadIdx.x >> 5;
    #pragma unroll
    for (int o = 16; o; o >>= 1) {
        float t = __shfl_xor_sync(0xffffffffu, v, o);
        v = ismax ? fmaxf(v, t) : (v + t);
    }
    if (lane == 0) sh[wid] = v;
    __syncthreads();
    int nw = (blockDim.x + 31) >> 5;
    if (wid == 0) {
        v = (lane < nw) ? sh[lane] : (ismax ? -1e30f : 0.f);
        #pragma unroll
        for (int o = 16; o; o >>= 1) {
            float t = __shfl_xor_sync(0xffffffffu, v, o);
            v = ismax ? fmaxf(v, t) : (v + t);
        }
        if (lane == 0) sh[0] = v;
    }
    __syncthreads();
    return sh[0];
}

__global__ void row_stats(const float* __restrict__ X, float* __restrict__ omax,
                          float* __restrict__ oinv, int len)
{
    const long row = blockIdx.x;
    const float* x = X + row * len;
    float m = -1e30f;
    for (int i = threadIdx.x; i < len; i += blockDim.x) m = fmaxf(m, x[i]);
    m = blockReduce(m, true);
    float s = 0.f;
    for (int i = threadIdx.x; i < len; i += blockDim.x) s += __expf(x[i] - m);
    s = blockReduce(s, false);
    if (threadIdx.x == 0) { omax[row] = m; oinv[row] = 1.f / s; }
}

__global__ void softmax_inplace(float* __restrict__ X, int len)
{
    const long row = blockIdx.x;
    float* x = X + row * len;
    float m = -1e30f;
    for (int i = threadIdx.x; i < len; i += blockDim.x) m = fmaxf(m, x[i]);
    m = blockReduce(m, true);
    float s = 0.f;
    for (int i = threadIdx.x; i < len; i += blockDim.x) s += __expf(x[i] - m);
    s = blockReduce(s, false);
    const float inv = 1.f / s;
    for (int i = threadIdx.x; i < len; i += blockDim.x) x[i] = __expf(x[i] - m) * inv;
}

__global__ void norm_rows256(float* __restrict__ V)
{
    const long row = blockIdx.x;
    float* v = V + row * 256;
    const float x = v[threadIdx.x];
    const float s = blockReduce(x * x, false);
    v[threadIdx.x] = x * (1.f / sqrtf(s));
}

__global__ void qcol_norm(const float* __restrict__ q, float* __restrict__ out)
{
    const int b = blockIdx.y;
    const int n = blockIdx.x * 256 + threadIdx.x;
    const float* p = q + (long)b * 256 * 4096 + n;
    float s = 0.f;
    #pragma unroll 8
    for (int c = 0; c < 256; c++) { float v = p[(long)c * 4096]; s += v * v; }
    out[b * 4096 + n] = 1.f / sqrtf(s);
}

__global__ void bn_stats(const float* __restrict__ y, float* __restrict__ mean,
                         float* __restrict__ istd)
{
    const int o = blockIdx.x;
    float s = 0.f, s2 = 0.f;
    for (int b = 0; b < 16; b++) {
        const float* p = y + ((long)b * 512 + o) * 4096;
        for (int i = threadIdx.x; i < 4096; i += 256) {
            float v = p[i]; s += v; s2 += v * v;
        }
    }
    s = blockReduce(s, false);
    s2 = blockReduce(s2, false);
    if (threadIdx.x == 0) {
        float mu = s * (1.f / 65536.f);
        mean[o] = mu;
        istd[o] = 1.f / sqrtf(s2 * (1.f / 65536.f) - mu * mu + 1e-5f);
    }
}

__global__ void bn_apply(float* __restrict__ y, const float* __restrict__ mean,
                         const float* __restrict__ istd, const float* __restrict__ g,
                         const float* __restrict__ b)
{
    const long i = (long)blockIdx.x * 256 + threadIdx.x;
    const int o = (int)((i >> 12) & 511);
    float v = (y[i] - mean[o]) * istd[o] * g[o] + b[o];
    y[i] = v > 0.f ? v : 0.f;
}

// ---------------------------------------------------------------------------
// Host orchestration
// ---------------------------------------------------------------------------
struct Scratch {
    float *kf, *kmax, *kinv, *qmax, *qinvs, *kpbs, *qpb, *sim, *value, *qcol, *cm, *mean, *istd;
};

static Scratch fetch_scratch() {
    Scratch s;
    cudaGetSymbolAddress((void**)&s.kf,    g_kf);
    cudaGetSymbolAddress((void**)&s.kmax,  g_kmax);
    cudaGetSymbolAddress((void**)&s.kinv,  g_kinv);
    cudaGetSymbolAddress((void**)&s.qmax,  g_qmax);
    cudaGetSymbolAddress((void**)&s.qinvs, g_qinvs);
    cudaGetSymbolAddress((void**)&s.kpbs,  g_kpbs);
    cudaGetSymbolAddress((void**)&s.qpb,   g_qpb);
    cudaGetSymbolAddress((void**)&s.sim,   g_sim);
    cudaGetSymbolAddress((void**)&s.value, g_value);
    cudaGetSymbolAddress((void**)&s.qcol,  g_qcol);
    cudaGetSymbolAddress((void**)&s.cm,    g_cm);
    cudaGetSymbolAddress((void**)&s.mean,  g_mean);
    cudaGetSymbolAddress((void**)&s.istd,  g_istd);
    cudaFuncSetAttribute(mgemm<false, false, true,  false>, cudaFuncAttributeMaxDynamicSharedMemorySize, TG_SMEM);
    cudaFuncSetAttribute(mgemm<true,  true,  false, false>, cudaFuncAttributeMaxDynamicSharedMemorySize, TG_SMEM);
    cudaFuncSetAttribute(mgemm<true,  false, false, false>, cudaFuncAttributeMaxDynamicSharedMemorySize, TG_SMEM);
    cudaFuncSetAttribute(mgemm<false, false, false, false>, cudaFuncAttributeMaxDynamicSharedMemorySize, TG_SMEM);
    cudaFuncSetAttribute(mgemm<false, false, true,  true >, cudaFuncAttributeMaxDynamicSharedMemorySize, TG_SMEM);
    return s;
}

extern "C" void kernel_launch(void* const* d_in, const int* in_sizes, int n_in,
                              void* d_out, int out_size)
{
    (void)in_sizes; (void)n_in; (void)out_size;
    static Scratch s = fetch_scratch();  // first call is the non-captured correctness run

    const float* x     = (const float*)d_in[0];
    const float* query = (const float*)d_in[1];
    const float* refs  = (const float*)d_in[2];
    const float* K_w   = (const float*)d_in[3];
    const float* K_b   = (const float*)d_in[4];
    // d_in[5], d_in[6] = V_w, V_b : dead code in the reference.
    const float* f_w   = (const float*)d_in[7];
    const float* f_b   = (const float*)d_in[8];
    const float* bn_g  = (const float*)d_in[9];
    const float* bn_b  = (const float*)d_in[10];
    float* out = (float*)d_out;

    // 1) kf[z] = K_w @ refs[z] + K_b   (NN, bias)  z = i*16+b
    mgemm<false, false, true, false><<<dim3(32, 2, 48), 256, TG_SMEM>>>(
        K_w, refs, s.kf, 256, 4096, 512, 0, 512L * 4096,
        48, 256L * 4096, 0, 4096,
        nullptr, nullptr, K_b, nullptr, 0, 0, nullptr, 1.f);

    // 2) softmax row stats
    row_stats<<<48 * 256, 256>>>(s.kf, s.kmax, s.kinv, 4096);
    row_stats<<<16 * 256, 256>>>(query, s.qmax, s.qinvs, 4096);

    // 3) k_pb[z] = softmax(kf[z]) @ kf[z]^T  (TB, EXPA) -> kpbs[b][i*256+k][c]
    mgemm<true, true, false, false><<<dim3(2, 2, 48), 256, TG_SMEM>>>(
        s.kf, s.kf, s.kpbs, 256, 256, 4096, 256L * 4096, 256L * 4096,
        16, 768L * 256, 256L * 256, 256,
        s.kmax, s.kinv, nullptr, nullptr, 0, 0, nullptr, 1.f);

    // 4) q_pb[b] = softmax(query[b]) @ query[b]^T
    mgemm<true, true, false, false><<<dim3(2, 2, 16), 256, TG_SMEM>>>(
        query, query, s.qpb, 256, 256, 4096, 256L * 4096, 256L * 4096,
        16, 256L * 256, 0, 256,
        s.qmax, s.qinvs, nullptr, nullptr, 0, 0, nullptr, 1.f);

    // 5) sim = (q_pb @ k_pbs^T) / sqrt(256)
    mgemm<true, false, false, false><<<dim3(6, 2, 16), 256, TG_SMEM>>>(
        s.qpb, s.kpbs, s.sim, 256, 768, 256, 256L * 256, 768L * 256,
        16, 256L * 768, 0, 768,
        nullptr, nullptr, nullptr, nullptr, 0, 0, nullptr, 0.0625f);

    // 6) softmax over k
    softmax_inplace<<<16 * 256, 256>>>(s.sim, 768);

    // 7) value = sim @ k_pbs (NN)
    mgemm<false, false, false, false><<<dim3(2, 2, 16), 256, TG_SMEM>>>(
        s.sim, s.kpbs, s.value, 256, 256, 768, 256L * 768, 768L * 256,
        16, 256L * 256, 0, 256,
        nullptr, nullptr, nullptr, nullptr, 0, 0, nullptr, 1.f);

    // 8) normalize prototypes; query column norms
    norm_rows256<<<16 * 256, 256>>>(s.value);
    qcol_norm<<<dim3(16, 16), 256>>>(query, s.qcol);

    // 9) cm_raw = proto_n @ query  (column scale folded into stage 10 loader)
    mgemm<false, false, false, false><<<dim3(32, 2, 16), 256, TG_SMEM>>>(
        s.value, query, s.cm, 256, 4096, 256, 256L * 256, 256L * 4096,
        16, 256L * 4096, 0, 4096,
        nullptr, nullptr, nullptr, nullptr, 0, 0, nullptr, 1.f);

    // 10) y = f_w @ concat(x, cm * qcol) + f_b
    mgemm<false, false, true, true><<<dim3(32, 4, 16), 256, TG_SMEM>>>(
        f_w, x, out, 512, 4096, 768, 0, 512L * 4096,
        16, 512L * 4096, 0, 4096,
        nullptr, nullptr, f_b, s.cm, 256L * 4096, 512, s.qcol, 1.f);

    // 11) BatchNorm (batch stats) + ReLU
    bn_stats<<<512, 256>>>(out, s.mean, s.istd);
    bn_apply<<<131072, 256>>>(out, s.mean, s.istd, bn_g, bn_b);
}

// round 6
// speedup vs baseline: 1.7568x; 1.4631x over previous
#include <cuda_runtime.h>
#include <cuda_bf16.h>
#include <cstdint>
#include <stdint.h>
#include <math.h>

// ---------------------------------------------------------------------------
// Scratch (static __device__ arrays; no allocations anywhere)
// ---------------------------------------------------------------------------
__device__ float g_kf[48u * 256u * 4096u];   // 201 MB
__device__ float g_kmax[48 * 256];
__device__ float g_kinv[48 * 256];
__device__ float g_qmax[16 * 256];
__device__ float g_qinvs[16 * 256];
__device__ float g_kpbs[16 * 768 * 256];
__device__ float g_qpb[16 * 256 * 256];
__device__ float g_sim[16 * 256 * 768];
__device__ float g_value[16 * 256 * 256];
__device__ float g_qcol[16 * 4096];
__device__ float g_cm[16u * 256u * 4096u];   // 67 MB
__device__ float g_mean[512];
__device__ float g_istd[512];

// ---------------------------------------------------------------------------
// mma.sync helpers (plain sm_80+ PTX — valid under compute_103)
// ---------------------------------------------------------------------------
__device__ __forceinline__ uint32_t smem_u32(const void* p) {
    uint32_t a;
    asm("{ .reg .u64 t; cvta.to.shared.u64 t, %1; cvt.u32.u64 %0, t; }" : "=r"(a) : "l"(p));
    return a;
}
__device__ __forceinline__ void ldmat4(uint32_t& r0, uint32_t& r1, uint32_t& r2, uint32_t& r3,
                                       uint32_t addr) {
    asm volatile("ldmatrix.sync.aligned.m8n8.x4.shared.b16 {%0,%1,%2,%3}, [%4];"
                 : "=r"(r0), "=r"(r1), "=r"(r2), "=r"(r3) : "r"(addr));
}
__device__ __forceinline__ void mma16816(float* d, const uint32_t* a, const uint32_t* b) {
    asm volatile(
        "mma.sync.aligned.m16n8k16.row.col.f32.bf16.bf16.f32 "
        "{%0,%1,%2,%3}, {%4,%5,%6,%7}, {%8,%9}, {%0,%1,%2,%3};"
        : "+f"(d[0]), "+f"(d[1]), "+f"(d[2]), "+f"(d[3])
        : "r"(a[0]), "r"(a[1]), "r"(a[2]), "r"(a[3]), "r"(b[0]), "r"(b[1]));
}

// split fp32 -> bf16 hi + bf16 residual
__device__ __forceinline__ void split2(float f, unsigned short& u1, unsigned short& u2) {
    __nv_bfloat16 h1 = __float2bfloat16(f);
    float r = f - __bfloat162float(h1);
    __nv_bfloat16 h2 = __float2bfloat16(r);
    u1 = *reinterpret_cast<unsigned short*>(&h1);
    u2 = *reinterpret_cast<unsigned short*>(&h2);
}

// smem geometry (per buffer): A parts 128 rows, B parts 64 rows, 80 B rows.
static constexpr int ROWB    = 80;             // 32 bf16 + 8 pad
static constexpr int A_PART  = 128 * ROWB;     // 10240
static constexpr int B_PART  = 64 * ROWB;      // 5120
static constexpr int OFF_A1  = 0;
static constexpr int OFF_A2  = A_PART;
static constexpr int OFF_B1  = 2 * A_PART;             // 20480
static constexpr int OFF_B2  = 2 * A_PART + B_PART;    // 25600
static constexpr int BUFB    = 2 * A_PART + 2 * B_PART; // 30720
static constexpr int TG_SMEM = 2 * BUFB;               // 61440

// ---------------------------------------------------------------------------
// mma.sync bf16-split2 GEMM: C = alpha*(A' @ B') (+bias[r])
//   A: row-major [M,K]; EXPA: fused exp(a - rmax)*rinv per row
//   TB:  B row-major [N,K]   (C = A @ B^T)
//   !TB: B row-major [K,N]   (C = A @ B)
//   CONCAT (!TB only): k >= Ksplit reads B2 (per z) scaled by colscale[z*N+n]
// CTA tile 128x64, K chunks of 32. M%128==0, N%64==0, K%32==0.
// 8 warps in 4(m) x 2(n), warp tile 32x32. 2 CTAs/SM.
// ---------------------------------------------------------------------------
template<bool TB, bool EXPA, bool HASBIAS, bool CONCAT>
__global__ void __launch_bounds__(256, 2) mgemm(
    const float* __restrict__ A, const float* __restrict__ B, float* __restrict__ C,
    int M, int N, int K, long sAz, long sBz,
    int modB, long sCb, long sCr, int ldc,
    const float* __restrict__ rmax, const float* __restrict__ rinv,
    const float* __restrict__ bias,
    const float* __restrict__ B2, long sB2z, int Ksplit,
    const float* __restrict__ colscale, float alpha)
{
    extern __shared__ char smem[];
    const uint32_t sb = smem_u32(smem);
    const int tid = threadIdx.x;
    const int wid = tid >> 5;
    const int lane = tid & 31;
    const int z = blockIdx.z;
    const int bm = blockIdx.y * 128;
    const int bn = blockIdx.x * 64;
    const float* Ab = A + (long)z * sAz;
    const float* Bb = B + (long)z * sBz;

    // EXPA row stats: A loader rows are (tid>>3)+32j
    float smx[4], siv[4];
    if (EXPA) {
        #pragma unroll
        for (int j = 0; j < 4; j++) {
            const int r = bm + (tid >> 3) + 32 * j;
            smx[j] = rmax[(long)z * M + r];
            siv[j] = rinv[(long)z * M + r];
        }
    }

    const int nch = K >> 5;

    auto loadA = [&](int k0, float4* fa) {
        #pragma unroll
        for (int j = 0; j < 4; j++) {
            const int row = (tid >> 3) + 32 * j;
            const int c4 = tid & 7;
            fa[j] = *reinterpret_cast<const float4*>(Ab + (long)(bm + row) * K + k0 + c4 * 4);
        }
    };
    auto loadB = [&](int k0, float4* fb) {
        if (TB) {
            #pragma unroll
            for (int j = 0; j < 2; j++) {
                const int row = (tid >> 3) + 32 * j;
                const int c4 = tid & 7;
                fb[j] = *reinterpret_cast<const float4*>(Bb + (long)(bn + row) * K + k0 + c4 * 4);
            }
        } else {
            #pragma unroll
            for (int j = 0; j < 2; j++) {
                const int k = (tid >> 4) + 16 * j;
                const int n4 = tid & 15;
                const int kg = k0 + k;
                float4 f;
                if (CONCAT && kg >= Ksplit) {
                    f = *reinterpret_cast<const float4*>(
                        B2 + (long)z * sB2z + (long)(kg - Ksplit) * N + bn + n4 * 4);
                    const float4 c = *reinterpret_cast<const float4*>(
                        colscale + (long)z * N + bn + n4 * 4);
                    f.x *= c.x; f.y *= c.y; f.z *= c.z; f.w *= c.w;
                } else {
                    f = *reinterpret_cast<const float4*>(Bb + (long)kg * N + bn + n4 * 4);
                }
                fb[j] = f;
            }
        }
    };
    auto stashA = [&](int buf, const float4* fa) {
        char* a1 = smem + buf * BUFB + OFF_A1;
        char* a2 = smem + buf * BUFB + OFF_A2;
        #pragma unroll
        for (int j = 0; j < 4; j++) {
            const int row = (tid >> 3) + 32 * j;
            const int c4 = tid & 7;
            float4 f = fa[j];
            if (EXPA) {
                const float m = smx[j], v = siv[j];
                f.x = __expf(f.x - m) * v; f.y = __expf(f.y - m) * v;
                f.z = __expf(f.z - m) * v; f.w = __expf(f.w - m) * v;
            }
            unsigned short x1, x2, y1, y2, z1, z2, w1, w2;
            split2(f.x, x1, x2); split2(f.y, y1, y2);
            split2(f.z, z1, z2); split2(f.w, w1, w2);
            const int off = row * ROWB + c4 * 8;
            *reinterpret_cast<uint2*>(a1 + off) =
                make_uint2((uint32_t)x1 | ((uint32_t)y1 << 16), (uint32_t)z1 | ((uint32_t)w1 << 16));
            *reinterpret_cast<uint2*>(a2 + off) =
                make_uint2((uint32_t)x2 | ((uint32_t)y2 << 16), (uint32_t)z2 | ((uint32_t)w2 << 16));
        }
    };
    auto stashB = [&](int buf, const float4* fb) {
        char* b1 = smem + buf * BUFB + OFF_B1;
        char* b2 = smem + buf * BUFB + OFF_B2;
        if (TB) {
            #pragma unroll
            for (int j = 0; j < 2; j++) {
                const int row = (tid >> 3) + 32 * j;
                const int c4 = tid & 7;
                const float4 f = fb[j];
                unsigned short x1, x2, y1, y2, z1, z2, w1, w2;
                split2(f.x, x1, x2); split2(f.y, y1, y2);
                split2(f.z, z1, z2); split2(f.w, w1, w2);
                const int off = row * ROWB + c4 * 8;
                *reinterpret_cast<uint2*>(b1 + off) =
                    make_uint2((uint32_t)x1 | ((uint32_t)y1 << 16), (uint32_t)z1 | ((uint32_t)w1 << 16));
                *reinterpret_cast<uint2*>(b2 + off) =
                    make_uint2((uint32_t)x2 | ((uint32_t)y2 << 16), (uint32_t)z2 | ((uint32_t)w2 << 16));
            }
        } else {
            #pragma unroll
            for (int j = 0; j < 2; j++) {
                const int k = (tid >> 4) + 16 * j;
                const int n4 = tid & 15;
                const float ff[4] = {fb[j].x, fb[j].y, fb[j].z, fb[j].w};
                #pragma unroll
                for (int u = 0; u < 4; u++) {
                    unsigned short u1, u2;
                    split2(ff[u], u1, u2);
                    const int off = (n4 * 4 + u) * ROWB + k * 2;
                    *reinterpret_cast<unsigned short*>(b1 + off) = u1;
                    *reinterpret_cast<unsigned short*>(b2 + off) = u2;
                }
            }
        }
    };

    // prologue: chunk 0
    float4 fa[4], fb[2];
    loadA(0, fa); loadB(0, fb);
    stashA(0, fa); stashB(0, fb);
    __syncthreads();

    float d[2][4][4];
    #pragma unroll
    for (int i = 0; i < 2; i++)
        #pragma unroll
        for (int j = 0; j < 4; j++)
            #pragma unroll
            for (int q = 0; q < 4; q++) d[i][j][q] = 0.f;

    const int wm = (wid >> 1) * 32;   // warp m offset (4 warps)
    const int wn = (wid & 1) * 32;    // warp n offset (2 warps)
    const int lr = lane & 15;
    const int lc = lane >> 4;

    for (int ch = 0; ch < nch; ch++) {
        const bool hasNext = (ch + 1 < nch);
        if (hasNext) { loadA((ch + 1) * 32, fa); loadB((ch + 1) * 32, fb); }

        const uint32_t base = sb + (ch & 1) * BUFB;
        #pragma unroll
        for (int ks = 0; ks < 2; ks++) {
            const uint32_t koff = ks * 32 + lc * 16;
            uint32_t ah[2][4], al[2][4], bh[4][2], bl[4][2];
            #pragma unroll
            for (int mt = 0; mt < 2; mt++)
                ldmat4(ah[mt][0], ah[mt][1], ah[mt][2], ah[mt][3],
                       base + OFF_A1 + (wm + mt * 16 + lr) * ROWB + koff);
            #pragma unroll
            for (int bt = 0; bt < 2; bt++) {
                uint32_t r0, r1, r2, r3;
                ldmat4(r0, r1, r2, r3, base + OFF_B1 + (wn + bt * 16 + lr) * ROWB + koff);
                bh[2 * bt][0] = r0; bh[2 * bt][1] = r2;
                bh[2 * bt + 1][0] = r1; bh[2 * bt + 1][1] = r3;
            }
            // hi*hi
            #pragma unroll
            for (int mt = 0; mt < 2; mt++)
                #pragma unroll
                for (int nt = 0; nt < 4; nt++) mma16816(d[mt][nt], ah[mt], bh[nt]);
            // hi*lo
            #pragma unroll
            for (int bt = 0; bt < 2; bt++) {
                uint32_t r0, r1, r2, r3;
                ldmat4(r0, r1, r2, r3, base + OFF_B2 + (wn + bt * 16 + lr) * ROWB + koff);
                bl[2 * bt][0] = r0; bl[2 * bt][1] = r2;
                bl[2 * bt + 1][0] = r1; bl[2 * bt + 1][1] = r3;
            }
            #pragma unroll
            for (int mt = 0; mt < 2; mt++)
                #pragma unroll
                for (int nt = 0; nt < 4; nt++) mma16816(d[mt][nt], ah[mt], bl[nt]);
            // lo*hi
            #pragma unroll
            for (int mt = 0; mt < 2; mt++)
                ldmat4(al[mt][0], al[mt][1], al[mt][2], al[mt][3],
                       base + OFF_A2 + (wm + mt * 16 + lr) * ROWB + koff);
            #pragma unroll
            for (int mt = 0; mt < 2; mt++)
                #pragma unroll
                for (int nt = 0; nt < 4; nt++) mma16816(d[mt][nt], al[mt], bh[nt]);
        }
        if (hasNext) { stashA((ch + 1) & 1, fa); stashB((ch + 1) & 1, fb); }
        __syncthreads();
    }

    // epilogue
    const long coff = (long)(z % modB) * sCb + (long)(z / modB) * sCr;
    #pragma unroll
    for (int mt = 0; mt < 2; mt++) {
        const int r0 = bm + wm + mt * 16 + (lane >> 2);
        const float bi0 = HASBIAS ? bias[r0] : 0.f;
        const float bi8 = HASBIAS ? bias[r0 + 8] : 0.f;
        #pragma unroll
        for (int nt = 0; nt < 4; nt++) {
            const int c0 = bn + wn + nt * 8 + (lane & 3) * 2;
            float* p0 = C + coff + (long)r0 * ldc + c0;
            float* p1 = C + coff + (long)(r0 + 8) * ldc + c0;
            *reinterpret_cast<float2*>(p0) =
                make_float2(d[mt][nt][0] * alpha + bi0, d[mt][nt][1] * alpha + bi0);
            *reinterpret_cast<float2*>(p1) =
                make_float2(d[mt][nt][2] * alpha + bi8, d[mt][nt][3] * alpha + bi8);
        }
    }
}

// ---------------------------------------------------------------------------
// Reductions / elementwise helpers
// ---------------------------------------------------------------------------
__device__ __forceinline__ float blockReduce(float v, bool ismax) {
    __shared__ float sh[32];
    __syncthreads();
    int lane = threadIdx.x & 31, wid = threadIdx.x >> 5;
    #pragma unroll
    for (int o = 16; o; o >>= 1) {
        float t = __shfl_xor_sync(0xffffffffu, v, o);
        v = ismax ? fmaxf(v, t) : (v + t);
    }
    if (lane == 0) sh[wid] = v;
    __syncthreads();
    int nw = (blockDim.x + 31) >> 5;
    if (wid == 0) {
        v = (lane < nw) ? sh[lane] : (ismax ? -1e30f : 0.f);
        #pragma unroll
        for (int o = 16; o; o >>= 1) {
            float t = __shfl_xor_sync(0xffffffffu, v, o);
            v = ismax ? fmaxf(v, t) : (v + t);
        }
        if (lane == 0) sh[0] = v;
    }
    __syncthreads();
    return sh[0];
}

__global__ void row_stats(const float* __restrict__ X, float* __restrict__ omax,
                          float* __restrict__ oinv, int len)
{
    const long row = blockIdx.x;
    const float* x = X + row * len;
    float m = -1e30f;
    for (int i = threadIdx.x; i < len; i += blockDim.x) m = fmaxf(m, x[i]);
    m = blockReduce(m, true);
    float s = 0.f;
    for (int i = threadIdx.x; i < len; i += blockDim.x) s += __expf(x[i] - m);
    s = blockReduce(s, false);
    if (threadIdx.x == 0) { omax[row] = m; oinv[row] = 1.f / s; }
}

__global__ void softmax_inplace(float* __restrict__ X, int len)
{
    const long row = blockIdx.x;
    float* x = X + row * len;
    float m = -1e30f;
    for (int i = threadIdx.x; i < len; i += blockDim.x) m = fmaxf(m, x[i]);
    m = blockReduce(m, true);
    float s = 0.f;
    for (int i = threadIdx.x; i < len; i += blockDim.x) s += __expf(x[i] - m);
    s = blockReduce(s, false);
    const float inv = 1.f / s;
    for (int i = threadIdx.x; i < len; i += blockDim.x) x[i] = __expf(x[i] - m) * inv;
}

__global__ void norm_rows256(float* __restrict__ V)
{
    const long row = blockIdx.x;
    float* v = V + row * 256;
    const float x = v[threadIdx.x];
    const float s = blockReduce(x * x, false);
    v[threadIdx.x] = x * (1.f / sqrtf(s));
}

__global__ void qcol_norm(const float* __restrict__ q, float* __restrict__ out)
{
    const int b = blockIdx.y;
    const int n = blockIdx.x * 256 + threadIdx.x;
    const float* p = q + (long)b * 256 * 4096 + n;
    float s = 0.f;
    #pragma unroll 8
    for (int c = 0; c < 256; c++) { float v = p[(long)c * 4096]; s += v * v; }
    out[b * 4096 + n] = 1.f / sqrtf(s);
}

__global__ void bn_stats(const float* __restrict__ y, float* __restrict__ mean,
                         float* __restrict__ istd)
{
    const int o = blockIdx.x;
    float s = 0.f, s2 = 0.f;
    for (int b = 0; b < 16; b++) {
        const float* p = y + ((long)b * 512 + o) * 4096;
        for (int i = threadIdx.x; i < 4096; i += 256) {
            float v = p[i]; s += v; s2 += v * v;
        }
    }
    s = blockReduce(s, false);
    s2 = blockReduce(s2, false);
    if (threadIdx.x == 0) {
        float mu = s * (1.f / 65536.f);
        mean[o] = mu;
        istd[o] = 1.f / sqrtf(s2 * (1.f / 65536.f) - mu * mu + 1e-5f);
    }
}

__global__ void bn_apply(float* __restrict__ y, const float* __restrict__ mean,
                         const float* __restrict__ istd, const float* __restrict__ g,
                         const float* __restrict__ b)
{
    const long i = (long)blockIdx.x * 256 + threadIdx.x;
    const int o = (int)((i >> 12) & 511);
    float v = (y[i] - mean[o]) * istd[o] * g[o] + b[o];
    y[i] = v > 0.f ? v : 0.f;
}

// ---------------------------------------------------------------------------
// Host orchestration
// ---------------------------------------------------------------------------
struct Scratch {
    float *kf, *kmax, *kinv, *qmax, *qinvs, *kpbs, *qpb, *sim, *value, *qcol, *cm, *mean, *istd;
};

static Scratch fetch_scratch() {
    Scratch s;
    cudaGetSymbolAddress((void**)&s.kf,    g_kf);
    cudaGetSymbolAddress((void**)&s.kmax,  g_kmax);
    cudaGetSymbolAddress((void**)&s.kinv,  g_kinv);
    cudaGetSymbolAddress((void**)&s.qmax,  g_qmax);
    cudaGetSymbolAddress((void**)&s.qinvs, g_qinvs);
    cudaGetSymbolAddress((void**)&s.kpbs,  g_kpbs);
    cudaGetSymbolAddress((void**)&s.qpb,   g_qpb);
    cudaGetSymbolAddress((void**)&s.sim,   g_sim);
    cudaGetSymbolAddress((void**)&s.value, g_value);
    cudaGetSymbolAddress((void**)&s.qcol,  g_qcol);
    cudaGetSymbolAddress((void**)&s.cm,    g_cm);
    cudaGetSymbolAddress((void**)&s.mean,  g_mean);
    cudaGetSymbolAddress((void**)&s.istd,  g_istd);
    cudaFuncSetAttribute(mgemm<false, false, true,  false>, cudaFuncAttributeMaxDynamicSharedMemorySize, TG_SMEM);
    cudaFuncSetAttribute(mgemm<true,  true,  false, false>, cudaFuncAttributeMaxDynamicSharedMemorySize, TG_SMEM);
    cudaFuncSetAttribute(mgemm<true,  false, false, false>, cudaFuncAttributeMaxDynamicSharedMemorySize, TG_SMEM);
    cudaFuncSetAttribute(mgemm<false, false, false, false>, cudaFuncAttributeMaxDynamicSharedMemorySize, TG_SMEM);
    cudaFuncSetAttribute(mgemm<false, false, true,  true >, cudaFuncAttributeMaxDynamicSharedMemorySize, TG_SMEM);
    return s;
}

extern "C" void kernel_launch(void* const* d_in, const int* in_sizes, int n_in,
                              void* d_out, int out_size)
{
    (void)in_sizes; (void)n_in; (void)out_size;
    static Scratch s = fetch_scratch();  // first call is the non-captured correctness run

    const float* x     = (const float*)d_in[0];
    const float* query = (const float*)d_in[1];
    const float* refs  = (const float*)d_in[2];
    const float* K_w   = (const float*)d_in[3];
    const float* K_b   = (const float*)d_in[4];
    // d_in[5], d_in[6] = V_w, V_b : dead code in the reference.
    const float* f_w   = (const float*)d_in[7];
    const float* f_b   = (const float*)d_in[8];
    const float* bn_g  = (const float*)d_in[9];
    const float* bn_b  = (const float*)d_in[10];
    float* out = (float*)d_out;

    // 1) kf[z] = K_w @ refs[z] + K_b   (NN, bias)  z = i*16+b
    mgemm<false, false, true, false><<<dim3(64, 2, 48), 256, TG_SMEM>>>(
        K_w, refs, s.kf, 256, 4096, 512, 0, 512L * 4096,
        48, 256L * 4096, 0, 4096,
        nullptr, nullptr, K_b, nullptr, 0, 0, nullptr, 1.f);

    // 2) softmax row stats
    row_stats<<<48 * 256, 256>>>(s.kf, s.kmax, s.kinv, 4096);
    row_stats<<<16 * 256, 256>>>(query, s.qmax, s.qinvs, 4096);

    // 3) k_pb[z] = softmax(kf[z]) @ kf[z]^T  (TB, EXPA) -> kpbs[b][i*256+k][c]
    mgemm<true, true, false, false><<<dim3(4, 2, 48), 256, TG_SMEM>>>(
        s.kf, s.kf, s.kpbs, 256, 256, 4096, 256L * 4096, 256L * 4096,
        16, 768L * 256, 256L * 256, 256,
        s.kmax, s.kinv, nullptr, nullptr, 0, 0, nullptr, 1.f);

    // 4) q_pb[b] = softmax(query[b]) @ query[b]^T
    mgemm<true, true, false, false><<<dim3(4, 2, 16), 256, TG_SMEM>>>(
        query, query, s.qpb, 256, 256, 4096, 256L * 4096, 256L * 4096,
        16, 256L * 256, 0, 256,
        s.qmax, s.qinvs, nullptr, nullptr, 0, 0, nullptr, 1.f);

    // 5) sim = (q_pb @ k_pbs^T) / sqrt(256)
    mgemm<true, false, false, false><<<dim3(12, 2, 16), 256, TG_SMEM>>>(
        s.qpb, s.kpbs, s.sim, 256, 768, 256, 256L * 256, 768L * 256,
        16, 256L * 768, 0, 768,
        nullptr, nullptr, nullptr, nullptr, 0, 0, nullptr, 0.0625f);

    // 6) softmax over k
    softmax_inplace<<<16 * 256, 256>>>(s.sim, 768);

    // 7) value = sim @ k_pbs (NN)
    mgemm<false, false, false, false><<<dim3(4, 2, 16), 256, TG_SMEM>>>(
        s.sim, s.kpbs, s.value, 256, 256, 768, 256L * 768, 768L * 256,
        16, 256L * 256, 0, 256,
        nullptr, nullptr, nullptr, nullptr, 0, 0, nullptr, 1.f);

    // 8) normalize prototypes; query column norms
    norm_rows256<<<16 * 256, 256>>>(s.value);
    qcol_norm<<<dim3(16, 16), 256>>>(query, s.qcol);

    // 9) cm_raw = proto_n @ query  (column scale folded into stage 10 loader)
    mgemm<false, false, false, false><<<dim3(64, 2, 16), 256, TG_SMEM>>>(
        s.value, query, s.cm, 256, 4096, 256, 256L * 256, 256L * 4096,
        16, 256L * 4096, 0, 4096,
        nullptr, nullptr, nullptr, nullptr, 0, 0, nullptr, 1.f);

    // 10) y = f_w @ concat(x, cm * qcol) + f_b
    mgemm<false, false, true, true><<<dim3(64, 4, 16), 256, TG_SMEM>>>(
        f_w, x, out, 512, 4096, 768, 0, 512L * 4096,
        16, 512L * 4096, 0, 4096,
        nullptr, nullptr, f_b, s.cm, 256L * 4096, 512, s.qcol, 1.f);

    // 11) BatchNorm (batch stats) + ReLU
    bn_stats<<<512, 256>>>(out, s.mean, s.istd);
    bn_apply<<<131072, 256>>>(out, s.mean, s.istd, bn_g, bn_b);
}

// round 7
// speedup vs baseline: 2.1278x; 1.2112x over previous
#include <cuda_runtime.h>
#include <cuda_bf16.h>
#include <cstdint>
#include <stdint.h>
#include <math.h>

// ---------------------------------------------------------------------------
// Scratch (static __device__ arrays; no allocations anywhere)
// ---------------------------------------------------------------------------
__device__ float g_kf[48u * 256u * 4096u];   // 201 MB
__device__ float g_kmax[48 * 256];
__device__ float g_kinv[48 * 256];
__device__ float g_qmax[16 * 256];
__device__ float g_qinvs[16 * 256];
__device__ float g_kpbs[16 * 768 * 256];
__device__ float g_qpb[16 * 256 * 256];
__device__ float g_sim[16 * 256 * 768];
__device__ float g_value[16 * 256 * 256];
__device__ float g_qcol[16 * 4096];
__device__ float g_cm[16u * 256u * 4096u];   // 67 MB
__device__ float g_mean[512];
__device__ float g_istd[512];

// ---------------------------------------------------------------------------
// mma.sync helpers (plain sm_80+ PTX — valid under compute_103)
// ---------------------------------------------------------------------------
__device__ __forceinline__ uint32_t smem_u32(const void* p) {
    uint32_t a;
    asm("{ .reg .u64 t; cvta.to.shared.u64 t, %1; cvt.u32.u64 %0, t; }" : "=r"(a) : "l"(p));
    return a;
}
__device__ __forceinline__ void ldmat4(uint32_t& r0, uint32_t& r1, uint32_t& r2, uint32_t& r3,
                                       uint32_t addr) {
    asm volatile("ldmatrix.sync.aligned.m8n8.x4.shared.b16 {%0,%1,%2,%3}, [%4];"
                 : "=r"(r0), "=r"(r1), "=r"(r2), "=r"(r3) : "r"(addr));
}
__device__ __forceinline__ void mma16816(float* d, const uint32_t* a, const uint32_t* b) {
    asm volatile(
        "mma.sync.aligned.m16n8k16.row.col.f32.bf16.bf16.f32 "
        "{%0,%1,%2,%3}, {%4,%5,%6,%7}, {%8,%9}, {%0,%1,%2,%3};"
        : "+f"(d[0]), "+f"(d[1]), "+f"(d[2]), "+f"(d[3])
        : "r"(a[0]), "r"(a[1]), "r"(a[2]), "r"(a[3]), "r"(b[0]), "r"(b[1]));
}

// Truncating fp32 -> bf16 split helpers (PRMT-based, minimal instruction count)
__device__ __forceinline__ uint32_t pack_hi2(float a, float b) {
    uint32_t r;
    asm("prmt.b32 %0, %1, %2, 0x7632;" : "=r"(r)
        : "r"(__float_as_uint(a)), "r"(__float_as_uint(b)));
    return r;
}
__device__ __forceinline__ float fhi(float f) {
    return __uint_as_float(__float_as_uint(f) & 0xFFFF0000u);
}
// float4 -> (hi uint2, lo uint2): hi = truncated bf16 pairs, lo = bf16(residual)
__device__ __forceinline__ void split4(float4 f, uint2& hi, uint2& lo) {
    hi = make_uint2(pack_hi2(f.x, f.y), pack_hi2(f.z, f.w));
    const float rx = f.x - fhi(f.x), ry = f.y - fhi(f.y);
    const float rz = f.z - fhi(f.z), rw = f.w - fhi(f.w);
    lo = make_uint2(pack_hi2(rx, ry), pack_hi2(rz, rw));
}

// smem geometry (per buffer): A parts 128 rows, B parts 64 rows, 80 B rows.
static constexpr int ROWB    = 80;             // 32 bf16 + 8 pad
static constexpr int A_PART  = 128 * ROWB;     // 10240
static constexpr int B_PART  = 64 * ROWB;      // 5120
static constexpr int OFF_A1  = 0;
static constexpr int OFF_A2  = A_PART;
static constexpr int OFF_B1  = 2 * A_PART;             // 20480
static constexpr int OFF_B2  = 2 * A_PART + B_PART;    // 25600
static constexpr int BUFB    = 2 * A_PART + 2 * B_PART; // 30720
static constexpr int TG_SMEM = 2 * BUFB;               // 61440

// ---------------------------------------------------------------------------
// mma.sync bf16-split2 GEMM: C = alpha*(A' @ B') (+bias[r])
//   A: row-major [M,K]; EXPA: fused exp(a - rmax)*rinv per row
//   TB:  B row-major [N,K]   (C = A @ B^T)
//   !TB: B row-major [K,N]   (C = A @ B)
//   CONCAT (!TB only): k >= Ksplit reads B2 (per z) scaled by colscale[z*N+n]
// CTA tile 128x64, K chunks of 32. M%128==0, N%64==0, K%32==0, Ksplit%32==0.
// 8 warps in 4(m) x 2(n), warp tile 32x32. 2 CTAs/SM.
// ---------------------------------------------------------------------------
template<bool TB, bool EXPA, bool HASBIAS, bool CONCAT>
__global__ void __launch_bounds__(256, 2) mgemm(
    const float* __restrict__ A, const float* __restrict__ B, float* __restrict__ C,
    int M, int N, int K, long sAz, long sBz,
    int modB, long sCb, long sCr, int ldc,
    const float* __restrict__ rmax, const float* __restrict__ rinv,
    const float* __restrict__ bias,
    const float* __restrict__ B2, long sB2z, int Ksplit,
    const float* __restrict__ colscale, float alpha)
{
    extern __shared__ char smem[];
    const uint32_t sb = smem_u32(smem);
    const int tid = threadIdx.x;
    const int wid = tid >> 5;
    const int lane = tid & 31;
    const int z = blockIdx.z;
    const int bm = blockIdx.y * 128;
    const int bn = blockIdx.x * 64;
    const float* Ab = A + (long)z * sAz;
    const float* Bb = B + (long)z * sBz;

    // ---- A loader geometry: row = ar+32j, 4 consecutive k per thread ----
    const int ar = tid >> 3;
    const int ac4 = tid & 7;
    const float* gA0 = Ab + (long)(bm + ar) * K + ac4 * 4;   // advance +32 per chunk

    float smx[4], siv[4];
    if (EXPA) {
        #pragma unroll
        for (int j = 0; j < 4; j++) {
            const int r = bm + ar + 32 * j;
            smx[j] = rmax[(long)z * M + r];
            siv[j] = rinv[(long)z * M + r];
        }
    }

    // ---- B loader geometry ----
    const float* gB0 = nullptr;         // TB path base (advance +32/chunk)
    int bkp = 0, bn4 = 0;               // NN path
    float4 csc = make_float4(1.f, 1.f, 1.f, 1.f);
    if (TB) {
        gB0 = Bb + (long)(bn + ar) * K + ac4 * 4;
    } else {
        bkp = tid & 15;       // k-pair index: rows 2*bkp, 2*bkp+1 of chunk
        bn4 = tid >> 4;       // n quad: columns bn + bn4*4 .. +3
        if (CONCAT)
            csc = *reinterpret_cast<const float4*>(colscale + (long)z * N + bn + bn4 * 4);
    }

    const int nch = K >> 5;

    auto loadA = [&](int ch, float4* fa) {
        const float* p = gA0 + ch * 32;
        #pragma unroll
        for (int j = 0; j < 4; j++)
            fa[j] = *reinterpret_cast<const float4*>(p + (long)(32 * j) * K);
    };
    auto loadB = [&](int ch, float4* fb) {
        if (TB) {
            const float* p = gB0 + ch * 32;
            #pragma unroll
            for (int j = 0; j < 2; j++)
                fb[j] = *reinterpret_cast<const float4*>(p + (long)(32 * j) * K);
        } else {
            const int kg = ch * 32 + 2 * bkp;
            const float* src;
            if (CONCAT && kg >= Ksplit)
                src = B2 + (long)z * sB2z + (long)(kg - Ksplit) * N + bn + bn4 * 4;
            else
                src = Bb + (long)kg * N + bn + bn4 * 4;
            fb[0] = *reinterpret_cast<const float4*>(src);
            fb[1] = *reinterpret_cast<const float4*>(src + N);
            if (CONCAT && kg >= Ksplit) {
                fb[0].x *= csc.x; fb[0].y *= csc.y; fb[0].z *= csc.z; fb[0].w *= csc.w;
                fb[1].x *= csc.x; fb[1].y *= csc.y; fb[1].z *= csc.z; fb[1].w *= csc.w;
            }
        }
    };
    auto stashA = [&](int buf, const float4* fa) {
        char* a1 = smem + buf * BUFB + OFF_A1;
        char* a2 = smem + buf * BUFB + OFF_A2;
        #pragma unroll
        for (int j = 0; j < 4; j++) {
            float4 f = fa[j];
            if (EXPA) {
                const float m = smx[j], v = siv[j];
                f.x = __expf(f.x - m) * v; f.y = __expf(f.y - m) * v;
                f.z = __expf(f.z - m) * v; f.w = __expf(f.w - m) * v;
            }
            uint2 hi, lo;
            split4(f, hi, lo);
            const int off = (ar + 32 * j) * ROWB + ac4 * 8;
            *reinterpret_cast<uint2*>(a1 + off) = hi;
            *reinterpret_cast<uint2*>(a2 + off) = lo;
        }
    };
    auto stashB = [&](int buf, const float4* fb) {
        char* b1 = smem + buf * BUFB + OFF_B1;
        char* b2 = smem + buf * BUFB + OFF_B2;
        if (TB) {
            #pragma unroll
            for (int j = 0; j < 2; j++) {
                uint2 hi, lo;
                split4(fb[j], hi, lo);
                const int off = (ar + 32 * j) * ROWB + ac4 * 8;
                *reinterpret_cast<uint2*>(b1 + off) = hi;
                *reinterpret_cast<uint2*>(b2 + off) = lo;
            }
        } else {
            const float r0[4] = {fb[0].x, fb[0].y, fb[0].z, fb[0].w};
            const float r1[4] = {fb[1].x, fb[1].y, fb[1].z, fb[1].w};
            #pragma unroll
            for (int u = 0; u < 4; u++) {
                const uint32_t hi = pack_hi2(r0[u], r1[u]);
                const uint32_t lo = pack_hi2(r0[u] - fhi(r0[u]), r1[u] - fhi(r1[u]));
                const int off = (bn4 * 4 + u) * ROWB + bkp * 4;
                *reinterpret_cast<uint32_t*>(b1 + off) = hi;
                *reinterpret_cast<uint32_t*>(b2 + off) = lo;
            }
        }
    };

    // prologue: chunk 0
    float4 fa[4], fb[2];
    loadA(0, fa); loadB(0, fb);
    stashA(0, fa); stashB(0, fb);
    __syncthreads();

    float d[2][4][4];
    #pragma unroll
    for (int i = 0; i < 2; i++)
        #pragma unroll
        for (int j = 0; j < 4; j++)
            #pragma unroll
            for (int q = 0; q < 4; q++) d[i][j][q] = 0.f;

    const int wm = (wid >> 1) * 32;   // warp m offset (4 warps)
    const int wn = (wid & 1) * 32;    // warp n offset (2 warps)
    const int lr = lane & 15;
    const int lc = lane >> 4;

    for (int ch = 0; ch < nch; ch++) {
        const bool hasNext = (ch + 1 < nch);
        if (hasNext) { loadA(ch + 1, fa); loadB(ch + 1, fb); }

        const uint32_t base = sb + (ch & 1) * BUFB;
        #pragma unroll
        for (int ks = 0; ks < 2; ks++) {
            const uint32_t koff = ks * 32 + lc * 16;
            uint32_t ah[2][4], al[2][4], bh[4][2], bl[4][2];
            #pragma unroll
            for (int mt = 0; mt < 2; mt++)
                ldmat4(ah[mt][0], ah[mt][1], ah[mt][2], ah[mt][3],
                       base + OFF_A1 + (wm + mt * 16 + lr) * ROWB + koff);
            #pragma unroll
            for (int bt = 0; bt < 2; bt++) {
                uint32_t r0, r1, r2, r3;
                ldmat4(r0, r1, r2, r3, base + OFF_B1 + (wn + bt * 16 + lr) * ROWB + koff);
                bh[2 * bt][0] = r0; bh[2 * bt][1] = r2;
                bh[2 * bt + 1][0] = r1; bh[2 * bt + 1][1] = r3;
            }
            // hi*hi
            #pragma unroll
            for (int mt = 0; mt < 2; mt++)
                #pragma unroll
                for (int nt = 0; nt < 4; nt++) mma16816(d[mt][nt], ah[mt], bh[nt]);
            // hi*lo
            #pragma unroll
            for (int bt = 0; bt < 2; bt++) {
                uint32_t r0, r1, r2, r3;
                ldmat4(r0, r1, r2, r3, base + OFF_B2 + (wn + bt * 16 + lr) * ROWB + koff);
                bl[2 * bt][0] = r0; bl[2 * bt][1] = r2;
                bl[2 * bt + 1][0] = r1; bl[2 * bt + 1][1] = r3;
            }
            #pragma unroll
            for (int mt = 0; mt < 2; mt++)
                #pragma unroll
                for (int nt = 0; nt < 4; nt++) mma16816(d[mt][nt], ah[mt], bl[nt]);
            // lo*hi
            #pragma unroll
            for (int mt = 0; mt < 2; mt++)
                ldmat4(al[mt][0], al[mt][1], al[mt][2], al[mt][3],
                       base + OFF_A2 + (wm + mt * 16 + lr) * ROWB + koff);
            #pragma unroll
            for (int mt = 0; mt < 2; mt++)
                #pragma unroll
                for (int nt = 0; nt < 4; nt++) mma16816(d[mt][nt], al[mt], bh[nt]);
        }
        if (hasNext) { stashA((ch + 1) & 1, fa); stashB((ch + 1) & 1, fb); }
        __syncthreads();
    }

    // epilogue
    const long coff = (long)(z % modB) * sCb + (long)(z / modB) * sCr;
    #pragma unroll
    for (int mt = 0; mt < 2; mt++) {
        const int r0 = bm + wm + mt * 16 + (lane >> 2);
        const float bi0 = HASBIAS ? bias[r0] : 0.f;
        const float bi8 = HASBIAS ? bias[r0 + 8] : 0.f;
        #pragma unroll
        for (int nt = 0; nt < 4; nt++) {
            const int c0 = bn + wn + nt * 8 + (lane & 3) * 2;
            float* p0 = C + coff + (long)r0 * ldc + c0;
            float* p1 = C + coff + (long)(r0 + 8) * ldc + c0;
            *reinterpret_cast<float2*>(p0) =
                make_float2(d[mt][nt][0] * alpha + bi0, d[mt][nt][1] * alpha + bi0);
            *reinterpret_cast<float2*>(p1) =
                make_float2(d[mt][nt][2] * alpha + bi8, d[mt][nt][3] * alpha + bi8);
        }
    }
}

// ---------------------------------------------------------------------------
// Reductions / elementwise helpers
// ---------------------------------------------------------------------------
__device__ __forceinline__ float blockReduce(float v, bool ismax) {
    __shared__ float sh[32];
    __syncthreads();
    int lane = threadIdx.x & 31, wid = threadIdx.x >> 5;
    #pragma unroll
    for (int o = 16; o; o >>= 1) {
        float t = __shfl_xor_sync(0xffffffffu, v, o);
        v = ismax ? fmaxf(v, t) : (v + t);
    }
    if (lane == 0) sh[wid] = v;
    __syncthreads();
    int nw = (blockDim.x + 31) >> 5;
    if (wid == 0) {
        v = (lane < nw) ? sh[lane] : (ismax ? -1e30f : 0.f);
        #pragma unroll
        for (int o = 16; o; o >>= 1) {
            float t = __shfl_xor_sync(0xffffffffu, v, o);
            v = ismax ? fmaxf(v, t) : (v + t);
        }
        if (lane == 0) sh[0] = v;
    }
    __syncthreads();
    return sh[0];
}

__global__ void row_stats(const float* __restrict__ X, float* __restrict__ omax,
                          float* __restrict__ oinv, int len)
{
    const long row = blockIdx.x;
    const float* x = X + row * len;
    float m = -1e30f;
    for (int i = threadIdx.x; i < len; i += blockDim.x) m = fmaxf(m, x[i]);
    m = blockReduce(m, true);
    float s = 0.f;
    for (int i = threadIdx.x; i < len; i += blockDim.x) s += __expf(x[i] - m);
    s = blockReduce(s, false);
    if (threadIdx.x == 0) { omax[row] = m; oinv[row] = 1.f / s; }
}

__global__ void softmax_inplace(float* __restrict__ X, int len)
{
    const long row = blockIdx.x;
    float* x = X + row * len;
    float m = -1e30f;
    for (int i = threadIdx.x; i < len; i += blockDim.x) m = fmaxf(m, x[i]);
    m = blockReduce(m, true);
    float s = 0.f;
    for (int i = threadIdx.x; i < len; i += blockDim.x) s += __expf(x[i] - m);
    s = blockReduce(s, false);
    const float inv = 1.f / s;
    for (int i = threadIdx.x; i < len; i += blockDim.x) x[i] = __expf(x[i] - m) * inv;
}

__global__ void norm_rows256(float* __restrict__ V)
{
    const long row = blockIdx.x;
    float* v = V + row * 256;
    const float x = v[threadIdx.x];
    const float s = blockReduce(x * x, false);
    v[threadIdx.x] = x * (1.f / sqrtf(s));
}

__global__ void qcol_norm(const float* __restrict__ q, float* __restrict__ out)
{
    const int b = blockIdx.y;
    const int n = blockIdx.x * 256 + threadIdx.x;
    const float* p = q + (long)b * 256 * 4096 + n;
    float s = 0.f;
    #pragma unroll 8
    for (int c = 0; c < 256; c++) { float v = p[(long)c * 4096]; s += v * v; }
    out[b * 4096 + n] = 1.f / sqrtf(s);
}

__global__ void bn_stats(const float* __restrict__ y, float* __restrict__ mean,
                         float* __restrict__ istd)
{
    const int o = blockIdx.x;
    float s = 0.f, s2 = 0.f;
    for (int b = 0; b < 16; b++) {
        const float* p = y + ((long)b * 512 + o) * 4096;
        for (int i = threadIdx.x; i < 4096; i += 256) {
            float v = p[i]; s += v; s2 += v * v;
        }
    }
    s = blockReduce(s, false);
    s2 = blockReduce(s2, false);
    if (threadIdx.x == 0) {
        float mu = s * (1.f / 65536.f);
        mean[o] = mu;
        istd[o] = 1.f / sqrtf(s2 * (1.f / 65536.f) - mu * mu + 1e-5f);
    }
}

__global__ void bn_apply(float* __restrict__ y, const float* __restrict__ mean,
                         const float* __restrict__ istd, const float* __restrict__ g,
                         const float* __restrict__ b)
{
    const long i = (long)blockIdx.x * 256 + threadIdx.x;
    const int o = (int)((i >> 12) & 511);
    float v = (y[i] - mean[o]) * istd[o] * g[o] + b[o];
    y[i] = v > 0.f ? v : 0.f;
}

// ---------------------------------------------------------------------------
// Host orchestration
// ---------------------------------------------------------------------------
struct Scratch {
    float *kf, *kmax, *kinv, *qmax, *qinvs, *kpbs, *qpb, *sim, *value, *qcol, *cm, *mean, *istd;
};

static Scratch fetch_scratch() {
    Scratch s;
    cudaGetSymbolAddress((void**)&s.kf,    g_kf);
    cudaGetSymbolAddress((void**)&s.kmax,  g_kmax);
    cudaGetSymbolAddress((void**)&s.kinv,  g_kinv);
    cudaGetSymbolAddress((void**)&s.qmax,  g_qmax);
    cudaGetSymbolAddress((void**)&s.qinvs, g_qinvs);
    cudaGetSymbolAddress((void**)&s.kpbs,  g_kpbs);
    cudaGetSymbolAddress((void**)&s.qpb,   g_qpb);
    cudaGetSymbolAddress((void**)&s.sim,   g_sim);
    cudaGetSymbolAddress((void**)&s.value, g_value);
    cudaGetSymbolAddress((void**)&s.qcol,  g_qcol);
    cudaGetSymbolAddress((void**)&s.cm,    g_cm);
    cudaGetSymbolAddress((void**)&s.mean,  g_mean);
    cudaGetSymbolAddress((void**)&s.istd,  g_istd);
    cudaFuncSetAttribute(mgemm<false, false, true,  false>, cudaFuncAttributeMaxDynamicSharedMemorySize, TG_SMEM);
    cudaFuncSetAttribute(mgemm<true,  true,  false, false>, cudaFuncAttributeMaxDynamicSharedMemorySize, TG_SMEM);
    cudaFuncSetAttribute(mgemm<true,  false, false, false>, cudaFuncAttributeMaxDynamicSharedMemorySize, TG_SMEM);
    cudaFuncSetAttribute(mgemm<false, false, false, false>, cudaFuncAttributeMaxDynamicSharedMemorySize, TG_SMEM);
    cudaFuncSetAttribute(mgemm<false, false, true,  true >, cudaFuncAttributeMaxDynamicSharedMemorySize, TG_SMEM);
    return s;
}

extern "C" void kernel_launch(void* const* d_in, const int* in_sizes, int n_in,
                              void* d_out, int out_size)
{
    (void)in_sizes; (void)n_in; (void)out_size;
    static Scratch s = fetch_scratch();  // first call is the non-captured correctness run

    const float* x     = (const float*)d_in[0];
    const float* query = (const float*)d_in[1];
    const float* refs  = (const float*)d_in[2];
    const float* K_w   = (const float*)d_in[3];
    const float* K_b   = (const float*)d_in[4];
    // d_in[5], d_in[6] = V_w, V_b : dead code in the reference.
    const float* f_w   = (const float*)d_in[7];
    const float* f_b   = (const float*)d_in[8];
    const float* bn_g  = (const float*)d_in[9];
    const float* bn_b  = (const float*)d_in[10];
    float* out = (float*)d_out;

    // 1) kf[z] = K_w @ refs[z] + K_b   (NN, bias)  z = i*16+b
    mgemm<false, false, true, false><<<dim3(64, 2, 48), 256, TG_SMEM>>>(
        K_w, refs, s.kf, 256, 4096, 512, 0, 512L * 4096,
        48, 256L * 4096, 0, 4096,
        nullptr, nullptr, K_b, nullptr, 0, 0, nullptr, 1.f);

    // 2) softmax row stats
    row_stats<<<48 * 256, 256>>>(s.kf, s.kmax, s.kinv, 4096);
    row_stats<<<16 * 256, 256>>>(query, s.qmax, s.qinvs, 4096);

    // 3) k_pb[z] = softmax(kf[z]) @ kf[z]^T  (TB, EXPA) -> kpbs[b][i*256+k][c]
    mgemm<true, true, false, false><<<dim3(4, 2, 48), 256, TG_SMEM>>>(
        s.kf, s.kf, s.kpbs, 256, 256, 4096, 256L * 4096, 256L * 4096,
        16, 768L * 256, 256L * 256, 256,
        s.kmax, s.kinv, nullptr, nullptr, 0, 0, nullptr, 1.f);

    // 4) q_pb[b] = softmax(query[b]) @ query[b]^T
    mgemm<true, true, false, false><<<dim3(4, 2, 16), 256, TG_SMEM>>>(
        query, query, s.qpb, 256, 256, 4096, 256L * 4096, 256L * 4096,
        16, 256L * 256, 0, 256,
        s.qmax, s.qinvs, nullptr, nullptr, 0, 0, nullptr, 1.f);

    // 5) sim = (q_pb @ k_pbs^T) / sqrt(256)
    mgemm<true, false, false, false><<<dim3(12, 2, 16), 256, TG_SMEM>>>(
        s.qpb, s.kpbs, s.sim, 256, 768, 256, 256L * 256, 768L * 256,
        16, 256L * 768, 0, 768,
        nullptr, nullptr, nullptr, nullptr, 0, 0, nullptr, 0.0625f);

    // 6) softmax over k
    softmax_inplace<<<16 * 256, 256>>>(s.sim, 768);

    // 7) value = sim @ k_pbs (NN)
    mgemm<false, false, false, false><<<dim3(4, 2, 16), 256, TG_SMEM>>>(
        s.sim, s.kpbs, s.value, 256, 256, 768, 256L * 768, 768L * 256,
        16, 256L * 256, 0, 256,
        nullptr, nullptr, nullptr, nullptr, 0, 0, nullptr, 1.f);

    // 8) normalize prototypes; query column norms
    norm_rows256<<<16 * 256, 256>>>(s.value);
    qcol_norm<<<dim3(16, 16), 256>>>(query, s.qcol);

    // 9) cm_raw = proto_n @ query  (column scale folded into stage 10 loader)
    mgemm<false, false, false, false><<<dim3(64, 2, 16), 256, TG_SMEM>>>(
        s.value, query, s.cm, 256, 4096, 256, 256L * 256, 256L * 4096,
        16, 256L * 4096, 0, 4096,
        nullptr, nullptr, nullptr, nullptr, 0, 0, nullptr, 1.f);

    // 10) y = f_w @ concat(x, cm * qcol) + f_b
    mgemm<false, false, true, true><<<dim3(64, 4, 16), 256, TG_SMEM>>>(
        f_w, x, out, 512, 4096, 768, 0, 512L * 4096,
        16, 512L * 4096, 0, 4096,
        nullptr, nullptr, f_b, s.cm, 256L * 4096, 512, s.qcol, 1.f);

    // 11) BatchNorm (batch stats) + ReLU
    bn_stats<<<512, 256>>>(out, s.mean, s.istd);
    bn_apply<<<131072, 256>>>(out, s.mean, s.istd, bn_g, bn_b);
}